// round 11
// baseline (speedup 1.0000x reference)
#include <cuda_runtime.h>
#include <cuda_bf16.h>
#include <cstdint>

#define BATCH 16
#define NQ 2048
#define NK 2048
#define DHEAD 128
#define KBLOCKS 16
#define NTILES 4096                          // BATCH * (NQ/128) * (NK/128)
#define K1_GRID 296                          // 2 CTAs per SM, single wave
#define INV_SQRT_SCALE 0.08838834764831845f  // 1/sqrt(128)

// ---------------------------------------------------------------------------
// Global scratch: pre-split bf16 hi/lo copies of q, k, v + bit-packed mask.
// ---------------------------------------------------------------------------
#define TENSOR_ELEMS ((size_t)BATCH * NQ * DHEAD)
__device__ __align__(16) __nv_bfloat16 g_qh[TENSOR_ELEMS];
__device__ __align__(16) __nv_bfloat16 g_ql[TENSOR_ELEMS];
__device__ __align__(16) __nv_bfloat16 g_kh[TENSOR_ELEMS];
__device__ __align__(16) __nv_bfloat16 g_kl[TENSOR_ELEMS];
__device__ __align__(16) __nv_bfloat16 g_vh[TENSOR_ELEMS];
__device__ __align__(16) __nv_bfloat16 g_vl[TENSOR_ELEMS];
__device__ float g_partial[(size_t)BATCH * NQ * KBLOCKS];
__device__ int g_mask_mode;   // 0 = bytes, 1 = int32, 2 = float32
#define MBITS_WORDS ((size_t)BATCH * NQ * NK / 32)
__device__ __align__(16) uint32_t g_mbits[MBITS_WORDS];

// ---------------------------------------------------------------------------
// K1 smem: 2 bufs x 4 tensors (Qh,Ql,Kh,Kl), each 128 rows x 32 bf16, row
// stride 80 B. DEDICATED score staging (32 rows x 132 f32 = 16896 B) after
// the buffers so the cross-tile cp.async pipeline never collides with it.
// ---------------------------------------------------------------------------
#define K1_CH 10240                        // 128 * 80
#define K1_BUF(b) ((b) * 4 * K1_CH)        // 40960 per buf
#define K1_KH 20480                        // K tensors offset within buf
#define K1_STAGE 81920
#define SMEM_K1 (81920 + 32 * 132 * 4)     // 98816
#define SCSTRIDE 132

// ---------------------------------------------------------------------------
// K2 smem: att fp32 chunk (128 x 32, stride 144 B) x2 bufs; V chunk (32 x 128
// bf16 h+l, stride 272 B) x2 bufs; E (128 x 32 bf16 h+l, row stride 80 B)
// single; rd[128]. Ctx staging overlays [0, 67584).
// ---------------------------------------------------------------------------
#define K2_ATT(b) ((b) * 18432)            // 128*144
#define K2_OFF_V 36864
#define K2_V(b) (K2_OFF_V + (b) * 17408)   // vh 8704 + vl 8704
#define K2_OFF_E 71680                     // Eh 10240, El 10240
#define K2_ESTRIDE 80
#define K2_EL 10240
#define K2_OFF_RD 92160
#define SMEM_K2 92672
#define K2_SCSTRIDE 132

// ---------------------------------------------------------------------------
// PTX primitives (portable, base sm_103 target)
// ---------------------------------------------------------------------------
__device__ __forceinline__ uint32_t smem_u32(const void* p) {
    uint32_t a;
    asm("{ .reg .u64 t; cvta.to.shared.u64 t, %1; cvt.u32.u64 %0, t; }" : "=r"(a) : "l"(p));
    return a;
}
__device__ __forceinline__ void ldsm_x4(uint32_t a, uint32_t r[4]) {
    asm volatile("ldmatrix.sync.aligned.m8n8.x4.shared.b16 {%0,%1,%2,%3}, [%4];"
        : "=r"(r[0]), "=r"(r[1]), "=r"(r[2]), "=r"(r[3]) : "r"(a));
}
__device__ __forceinline__ void ldsm_x2(uint32_t a, uint32_t r[2]) {
    asm volatile("ldmatrix.sync.aligned.m8n8.x2.shared.b16 {%0,%1}, [%2];"
        : "=r"(r[0]), "=r"(r[1]) : "r"(a));
}
__device__ __forceinline__ void ldsm_x4t(uint32_t a, uint32_t r[4]) {
    asm volatile("ldmatrix.sync.aligned.m8n8.x4.trans.shared.b16 {%0,%1,%2,%3}, [%4];"
        : "=r"(r[0]), "=r"(r[1]), "=r"(r[2]), "=r"(r[3]) : "r"(a));
}
__device__ __forceinline__ void mma16816(float c[4], const uint32_t a[4], uint32_t b0, uint32_t b1) {
    asm volatile("mma.sync.aligned.m16n8k16.row.col.f32.bf16.bf16.f32 "
        "{%0,%1,%2,%3}, {%4,%5,%6,%7}, {%8,%9}, {%0,%1,%2,%3};"
        : "+f"(c[0]), "+f"(c[1]), "+f"(c[2]), "+f"(c[3])
        : "r"(a[0]), "r"(a[1]), "r"(a[2]), "r"(a[3]), "r"(b0), "r"(b1));
}
__device__ __forceinline__ void cp16(uint32_t dst, const void* src) {
    asm volatile("cp.async.cg.shared.global [%0], [%1], 16;" :: "r"(dst), "l"(src));
}
#define CP_COMMIT() asm volatile("cp.async.commit_group;")
#define CP_WAIT1()  asm volatile("cp.async.wait_group 1;")
#define CP_WAIT0()  asm volatile("cp.async.wait_group 0;")

__device__ __forceinline__ uint32_t pack2(__nv_bfloat16 a, __nv_bfloat16 b) {
    __nv_bfloat162 t = __halves2bfloat162(a, b);
    return *reinterpret_cast<uint32_t*>(&t);
}
__device__ __forceinline__ void split2(float x, float y, uint32_t& h, uint32_t& l) {
    __nv_bfloat16 hx = __float2bfloat16(x), hy = __float2bfloat16(y);
    __nv_bfloat16 lx = __float2bfloat16(x - __bfloat162float(hx));
    __nv_bfloat16 ly = __float2bfloat16(y - __bfloat162float(hy));
    h = pack2(hx, hy);
    l = pack2(lx, ly);
}

// ---------------------------------------------------------------------------
__global__ void detect_mask_kernel(const unsigned char* __restrict__ m)
{
    const int tid = threadIdx.x;
    int mis = 0, ftail = 0;
    for (int i = tid * 16; i < tid * 16 + 16; i++) {
        const unsigned char b = m[i];
        if (b) {
            const int r = i & 3;
            if (r == 1) mis = 1;
            else if (r == 2) { if (b != 0x80) mis = 1; else ftail = 1; }
            else if (r == 3) { if (b != 0x3F) mis = 1; else ftail = 1; }
        }
    }
    const int anyMis = __syncthreads_or(mis);
    const int anyF   = __syncthreads_or(ftail);
    if (tid == 0) g_mask_mode = anyMis ? 0 : (anyF ? 2 : 1);
}

__global__ __launch_bounds__(256) void pack_mask_kernel(const void* __restrict__ mask)
{
    const size_t w = (size_t)blockIdx.x * 256 + threadIdx.x;
    const int mode = g_mask_mode;
    uint32_t bits = 0;
    if (mode == 0) {
        const uint4* p = (const uint4*)((const unsigned char*)mask + w * 32);
#pragma unroll
        for (int i = 0; i < 2; i++) {
            const uint4 v = p[i];
            const uint32_t ws[4] = {v.x, v.y, v.z, v.w};
#pragma unroll
            for (int k = 0; k < 4; k++)
#pragma unroll
                for (int byt = 0; byt < 4; byt++)
                    bits |= (uint32_t)(((ws[k] >> (8 * byt)) & 0xffu) != 0u) << (i * 16 + k * 4 + byt);
        }
    } else {
        const uint4* p = (const uint4*)((const uint32_t*)mask + w * 32);
#pragma unroll
        for (int i = 0; i < 8; i++) {
            const uint4 v = p[i];
            bits |= (uint32_t)(v.x != 0u) << (i * 4 + 0);
            bits |= (uint32_t)(v.y != 0u) << (i * 4 + 1);
            bits |= (uint32_t)(v.z != 0u) << (i * 4 + 2);
            bits |= (uint32_t)(v.w != 0u) << (i * 4 + 3);
        }
    }
    g_mbits[w] = bits;
}

__global__ __launch_bounds__(256) void prep_kernel(
    const float* __restrict__ q, const float* __restrict__ k, const float* __restrict__ v)
{
    const size_t t = (size_t)blockIdx.x * 256 + threadIdx.x;   // float4 index
    const float* src;
    __nv_bfloat16 *dh, *dl;
    if (blockIdx.y == 0)      { src = q; dh = g_qh; dl = g_ql; }
    else if (blockIdx.y == 1) { src = k; dh = g_kh; dl = g_kl; }
    else                      { src = v; dh = g_vh; dl = g_vl; }
    const float4 x = ((const float4*)src)[t];
    uint32_t h01, l01, h23, l23;
    split2(x.x, x.y, h01, l01);
    split2(x.z, x.w, h23, l23);
    ((uint2*)dh)[t] = make_uint2(h01, h23);
    ((uint2*)dl)[t] = make_uint2(l01, l23);
}

// ---------------------------------------------------------------------------
// K1 chunk issue (unchanged from R9): one 32-dim chunk of Q+K hi/lo tiles.
// ---------------------------------------------------------------------------
__device__ __forceinline__ void k1_issue(uint32_t sb, int b, int q0, int k0, int ic, int buf, int tid)
{
    const int d0 = ic * 32;
#pragma unroll
    for (int i = 0; i < 8; i++) {
        const int idx = i * 256 + tid;     // 0..2047
        const int t = idx >> 9;            // tensor 0..3
        const int r = (idx >> 2) & 127;
        const int c = idx & 3;
        const __nv_bfloat16* base = (t == 0) ? g_qh : (t == 1) ? g_ql : (t == 2) ? g_kh : g_kl;
        const int row0 = (t < 2) ? q0 : k0;
        cp16(sb + K1_BUF(buf) + t * K1_CH + r * 80 + c * 16,
             base + ((size_t)(b * NQ + row0 + r)) * DHEAD + d0 + c * 8);
    }
}

// ---------------------------------------------------------------------------
// K1 (persistent): 296 CTAs loop over 4096 tiles; continuous cross-tile
// cp.async pipeline; epilogue in 4 passes of 32 rows via dedicated staging.
// ---------------------------------------------------------------------------
__global__ __launch_bounds__(256, 2)
void qk_exp_kernel(float* __restrict__ att)
{
    extern __shared__ char smem[];
    const uint32_t sb = smem_u32(smem);
    float* sc = (float*)(smem + K1_STAGE);
    const int tid = threadIdx.x;
    const int wid = tid >> 5;
    const int lane = tid & 31;
    const int wm = wid & 1;     // 64-row half
    const int wn = wid >> 1;    // 32-col group
    const int lm = lane & 15, lq = lane >> 4;
    const int bn = lane & 7,  bk = (lane >> 3) & 1;

    const int my_ntiles = (NTILES - blockIdx.x + K1_GRID - 1) / K1_GRID;
    const int gmax = my_ntiles * 4;

    // issue global-chunk g (or an empty group past the end, to keep counts).
    auto issue_g = [&](int g) {
        if (g < gmax) {
            const int t = blockIdx.x + (g >> 2) * K1_GRID;
            k1_issue(sb, t >> 8, ((t >> 4) & 15) * 128, (t & 15) * 128, g & 3, g & 1, tid);
        }
        CP_COMMIT();
    };

    issue_g(0);
    issue_g(1);

    for (int j = 0; j < my_ntiles; j++) {
        const int t  = blockIdx.x + j * K1_GRID;
        const int b  = t >> 8;
        const int q0 = ((t >> 4) & 15) * 128;
        const int k0 = (t & 15) * 128;

        float acc[4][4][4];
#pragma unroll
        for (int mt = 0; mt < 4; mt++)
#pragma unroll
            for (int nt = 0; nt < 4; nt++)
#pragma unroll
                for (int r = 0; r < 4; r++) acc[mt][nt][r] = 0.0f;

        for (int c = 0; c < 4; c++) {
            const int g = j * 4 + c;
            const int buf = g & 1;
            CP_WAIT1();
            __syncthreads();

            const uint32_t qb = sb + K1_BUF(buf);
            const uint32_t kb = sb + K1_BUF(buf) + K1_KH;
#pragma unroll
            for (int ks = 0; ks < 2; ks++) {
                uint32_t ah[4][4], al[4][4], bh[4][2], bl[4][2];
#pragma unroll
                for (int mt = 0; mt < 4; mt++) {
                    const uint32_t a = qb + (wm * 64 + mt * 16 + lm) * 80 + (ks * 16 + lq * 8) * 2;
                    ldsm_x4(a, ah[mt]);
                    ldsm_x4(a + K1_CH, al[mt]);
                }
#pragma unroll
                for (int nt = 0; nt < 4; nt++) {
                    const uint32_t a = kb + (wn * 32 + nt * 8 + bn) * 80 + (ks * 16 + bk * 8) * 2;
                    ldsm_x2(a, bh[nt]);
                    ldsm_x2(a + K1_CH, bl[nt]);
                }
#pragma unroll
                for (int mt = 0; mt < 4; mt++)
#pragma unroll
                    for (int nt = 0; nt < 4; nt++) {
                        mma16816(acc[mt][nt], ah[mt], bh[nt][0], bh[nt][1]);
                        mma16816(acc[mt][nt], ah[mt], bl[nt][0], bl[nt][1]);
                        mma16816(acc[mt][nt], al[mt], bh[nt][0], bh[nt][1]);
                    }
            }
            __syncthreads();
            issue_g(g + 2);     // next-tile chunks flow in during the epilogue
        }

        // ---- Epilogue: 4 passes of 32 rows through dedicated staging ----
#pragma unroll 1
        for (int p = 0; p < 4; p++) {
            __syncthreads();
            if (wm == (p >> 1)) {
                const int mtb = (p & 1) * 2;
#pragma unroll
                for (int m2 = 0; m2 < 2; m2++) {
                    const int mt = mtb + m2;
#pragma unroll
                    for (int nt = 0; nt < 4; nt++) {
                        const int rl = m2 * 16 + (lane >> 2);
                        const int cc = wn * 32 + nt * 8 + (lane & 3) * 2;
                        sc[rl * SCSTRIDE + cc]           = acc[mt][nt][0];
                        sc[rl * SCSTRIDE + cc + 1]       = acc[mt][nt][1];
                        sc[(rl + 8) * SCSTRIDE + cc]     = acc[mt][nt][2];
                        sc[(rl + 8) * SCSTRIDE + cc + 1] = acc[mt][nt][3];
                    }
                }
            }
            __syncthreads();

            const int rl = tid >> 3;           // 0..31
            const int ch = tid & 7;            // 16-col chunk
            const int rowg = q0 + p * 32 + rl;
            const uint32_t mword = g_mbits[((size_t)b * NQ + rowg) * (NK / 32) + (k0 >> 5) + (ch >> 1)];
            const uint32_t mbits = mword >> ((ch & 1) * 16);
            const size_t roff = ((size_t)b * NQ + rowg) * NK + k0 + ch * 16;
            float rsum = 0.0f;
#pragma unroll
            for (int jj = 0; jj < 4; jj++) {
                const float4 s4 = *(const float4*)&sc[rl * SCSTRIDE + ch * 16 + jj * 4];
                const float ss[4] = {s4.x, s4.y, s4.z, s4.w};
                float e[4];
#pragma unroll
                for (int q = 0; q < 4; q++)
                    e[q] = ((mbits >> (jj * 4 + q)) & 1u) ? 0.0f : __expf(ss[q] * INV_SQRT_SCALE);
                rsum += (e[0] + e[1]) + (e[2] + e[3]);
                *(float4*)(att + roff + jj * 4) = make_float4(e[0], e[1], e[2], e[3]);
            }
            rsum += __shfl_down_sync(0xffffffffu, rsum, 4);
            rsum += __shfl_down_sync(0xffffffffu, rsum, 2);
            rsum += __shfl_down_sync(0xffffffffu, rsum, 1);
            if ((lane & 7) == 0)
                g_partial[((size_t)b * NQ + rowg) * KBLOCKS + (k0 >> 7)] = rsum;
        }
    }
}

// ---------------------------------------------------------------------------
// K2: normalize att in place; ctx = att @ V. NK streamed in 32-key chunks,
// cp.async double-buffered (att fp32 + pre-split V). Unchanged from R9.
// ---------------------------------------------------------------------------
__device__ __forceinline__ void k2_issue(uint32_t sb, const float* attbase, int b, int ic, int buf, int tid)
{
    const int n0 = ic * 32;
#pragma unroll
    for (int i = 0; i < 8; i++) {
        const int idx = i * 256 + tid;     // 0..2047
        if (idx < 1024) {                  // att fp32 chunk: 128 rows x 8 c16
            const int r = idx >> 3;
            const int c = idx & 7;
            cp16(sb + K2_ATT(buf) + r * 144 + c * 16,
                 attbase + (size_t)r * NK + n0 + c * 4);
        } else {                           // V h/l: 32 rows x 16 c16 each
            const int j = idx - 1024;
            const int h = j >> 9;
            const int r = (j >> 4) & 31;
            const int c = j & 15;
            const __nv_bfloat16* base = h ? g_vl : g_vh;
            cp16(sb + K2_V(buf) + h * 8704 + r * 272 + c * 16,
                 base + ((size_t)(b * NK + n0 + r)) * DHEAD + c * 8);
        }
    }
}

__global__ __launch_bounds__(256, 2)
void av_kernel(float* __restrict__ att, float* __restrict__ ctx)
{
    extern __shared__ char smem[];
    const uint32_t sb = smem_u32(smem);
    float* rd = (float*)(smem + K2_OFF_RD);
    const int tid = threadIdx.x;
    const int wid = tid >> 5;
    const int lane = tid & 31;
    const int wm = wid & 1;
    const int wn = wid >> 1;

    const int b  = blockIdx.y;
    const int q0 = blockIdx.x * 128;

    if (tid < 128) {
        const float* p = &g_partial[((size_t)b * NQ + q0 + tid) * KBLOCKS];
        float s = 0.0f;
#pragma unroll
        for (int i = 0; i < KBLOCKS; i++) s += p[i];
        rd[tid] = 1.0f / s;
    }

    float* attbase = att + ((size_t)b * NQ + q0) * NK;
    k2_issue(sb, attbase, b, 0, 0, tid); CP_COMMIT();
    k2_issue(sb, attbase, b, 1, 1, tid); CP_COMMIT();

    float acc[4][4][4];
#pragma unroll
    for (int mt = 0; mt < 4; mt++)
#pragma unroll
        for (int nt = 0; nt < 4; nt++)
#pragma unroll
            for (int r = 0; r < 4; r++) acc[mt][nt][r] = 0.0f;

    const int lm = lane & 15, lq = lane >> 4;

    for (int ic = 0; ic < NK / 32; ic++) {
        const int buf = ic & 1;
        const int n0 = ic * 32;
        if (ic < NK / 32 - 1) { CP_WAIT1(); } else { CP_WAIT0(); }
        __syncthreads();

        // Normalize att chunk (write back to global) + split into E tiles.
#pragma unroll
        for (int i = 0; i < 4; i++) {
            const int idx = i * 256 + tid;    // 0..1023
            const int r = idx >> 3;
            const int c4 = idx & 7;
            float4 e = *(const float4*)(smem + K2_ATT(buf) + r * 144 + c4 * 16);
            const float rr = rd[r];
            e.x *= rr; e.y *= rr; e.z *= rr; e.w *= rr;
            *(float4*)(attbase + (size_t)r * NK + n0 + c4 * 4) = e;
            uint32_t hh0, ll0, hh1, ll1;
            split2(e.x, e.y, hh0, ll0);
            split2(e.z, e.w, hh1, ll1);
            *(uint2*)(smem + K2_OFF_E + r * K2_ESTRIDE + c4 * 8)         = make_uint2(hh0, hh1);
            *(uint2*)(smem + K2_OFF_E + K2_EL + r * K2_ESTRIDE + c4 * 8) = make_uint2(ll0, ll1);
        }
        __syncthreads();

        const uint32_t vb = sb + K2_V(buf);
#pragma unroll
        for (int ks = 0; ks < 2; ks++) {
            uint32_t eh[4][4], el[4][4];
#pragma unroll
            for (int mt = 0; mt < 4; mt++) {
                const uint32_t a = sb + K2_OFF_E + (wm * 64 + mt * 16 + lm) * K2_ESTRIDE
                                 + (ks * 16 + lq * 8) * 2;
                ldsm_x4(a, eh[mt]);
                ldsm_x4(a + K2_EL, el[mt]);
            }
#pragma unroll
            for (int ntp = 0; ntp < 2; ntp++) {
                uint32_t vh4[4], vl4[4];
                const uint32_t a = vb + (ks * 16 + lm) * 272 + (wn * 32 + ntp * 16 + lq * 8) * 2;
                ldsm_x4t(a, vh4);
                ldsm_x4t(a + 8704, vl4);
#pragma unroll
                for (int mt = 0; mt < 4; mt++) {
                    mma16816(acc[mt][ntp * 2],     eh[mt], vh4[0], vh4[1]);
                    mma16816(acc[mt][ntp * 2 + 1], eh[mt], vh4[2], vh4[3]);
                }
#pragma unroll
                for (int mt = 0; mt < 4; mt++) {
                    mma16816(acc[mt][ntp * 2],     eh[mt], vl4[0], vl4[1]);
                    mma16816(acc[mt][ntp * 2 + 1], eh[mt], vl4[2], vl4[3]);
                }
#pragma unroll
                for (int mt = 0; mt < 4; mt++) {
                    mma16816(acc[mt][ntp * 2],     el[mt], vh4[0], vh4[1]);
                    mma16816(acc[mt][ntp * 2 + 1], el[mt], vh4[2], vh4[3]);
                }
            }
        }
        __syncthreads();
        if (ic + 2 < NK / 32) { k2_issue(sb, attbase, b, ic + 2, (ic + 2) & 1, tid); CP_COMMIT(); }
    }

    // Stage ctx through smem for coalesced writes (overlays buffers).
    float* sc = (float*)smem;
    {
        const int r0 = lane >> 2;
        const int c0 = (lane & 3) * 2;
#pragma unroll
        for (int mt = 0; mt < 4; mt++)
#pragma unroll
            for (int nt = 0; nt < 4; nt++) {
                const int rr = wm * 64 + mt * 16 + r0;
                const int cc = wn * 32 + nt * 8 + c0;
                sc[rr * K2_SCSTRIDE + cc]           = acc[mt][nt][0];
                sc[rr * K2_SCSTRIDE + cc + 1]       = acc[mt][nt][1];
                sc[(rr + 8) * K2_SCSTRIDE + cc]     = acc[mt][nt][2];
                sc[(rr + 8) * K2_SCSTRIDE + cc + 1] = acc[mt][nt][3];
            }
    }
    __syncthreads();
    {
        const int row  = tid & 127;
        const int half = tid >> 7;
        float* o = ctx + ((size_t)b * NQ + q0 + row) * DHEAD + half * 64;
#pragma unroll
        for (int j = 0; j < 16; j++)
            *(float4*)(o + j * 4) = *(const float4*)&sc[row * K2_SCSTRIDE + half * 64 + j * 4];
    }
}

// ---------------------------------------------------------------------------
extern "C" void kernel_launch(void* const* d_in, const int* in_sizes, int n_in,
                              void* d_out, int out_size)
{
    const float* q = (const float*)d_in[0];
    const float* k = (const float*)d_in[1];
    const float* v = (const float*)d_in[2];
    const void*  mask = d_in[3];

    float* out = (float*)d_out;
    float* ctx = out;                                   // [B, NQ, D]
    float* att = out + (size_t)BATCH * NQ * DHEAD;      // [B, NQ, NK]

    cudaFuncSetAttribute(qk_exp_kernel, cudaFuncAttributeMaxDynamicSharedMemorySize, SMEM_K1);
    cudaFuncSetAttribute(av_kernel,     cudaFuncAttributeMaxDynamicSharedMemorySize, SMEM_K2);

    detect_mask_kernel<<<1, 256>>>((const unsigned char*)mask);
    pack_mask_kernel<<<(int)(MBITS_WORDS / 256), 256>>>(mask);
    prep_kernel<<<dim3(4096, 3), 256>>>(q, k, v);

    qk_exp_kernel<<<K1_GRID, 256, SMEM_K1>>>(att);

    dim3 g2(NQ / 128, BATCH);
    av_kernel<<<g2, 256, SMEM_K2>>>(att, ctx);
}

// round 14
// speedup vs baseline: 1.5053x; 1.5053x over previous
// ---------------------------------------------------------------------------
// THEORY (R14 = R12 design, resubmitted after two submission-format failures):
//   - K1 stores unnormalized E as fp16 into g_e scratch (134 MB) instead of
//     fp32 into att (268 MB): -134 MB writes in K1, -134 MB reads in K2.
//     fp16 RN rel error bound 2^-11 ~ 4.9e-4 < 1e-3; row sums computed from
//     the ROUNDED values so softmax rows stay exactly self-consistent.
//   - K2: E is already fp16 -> A needs no hi/lo split -> 2-term fp16 MMA
//     (E@Vh + E@Vl, V pre-split fp16 hi/lo = 22-bit mantissa). MMA work x2/3.
//     The fp32 att output (= E * 1/denom) is written inside K2's mainloop
//     from the E smem chunk; ctx normalized at the epilogue.
//   Prediction: K1 219 -> ~195 us, K2 161 -> ~115-125 us,
//   total 455 -> ~385-400 us; rel_err ~2-4e-4 (deterministic).
// ---------------------------------------------------------------------------
#include <cuda_runtime.h>
#include <cuda_bf16.h>
#include <cuda_fp16.h>
#include <cstdint>

#define BATCH 16
#define NQ 2048
#define NK 2048
#define DHEAD 128
#define KBLOCKS 16
#define INV_SQRT_SCALE 0.08838834764831845f  // 1/sqrt(128)

// ---------------------------------------------------------------------------
// Global scratch: bf16 hi/lo Q,K; fp16 hi/lo V; fp16 unnormalized E; bit mask.
// ---------------------------------------------------------------------------
#define TENSOR_ELEMS ((size_t)BATCH * NQ * DHEAD)
__device__ __align__(16) __nv_bfloat16 g_qh[TENSOR_ELEMS];
__device__ __align__(16) __nv_bfloat16 g_ql[TENSOR_ELEMS];
__device__ __align__(16) __nv_bfloat16 g_kh[TENSOR_ELEMS];
__device__ __align__(16) __nv_bfloat16 g_kl[TENSOR_ELEMS];
__device__ __align__(16) __half g_vh[TENSOR_ELEMS];
__device__ __align__(16) __half g_vl[TENSOR_ELEMS];
__device__ __align__(16) __half g_e[(size_t)BATCH * NQ * NK];   // 134 MB
__device__ float g_partial[(size_t)BATCH * NQ * KBLOCKS];
__device__ int g_mask_mode;   // 0 = bytes, 1 = int32, 2 = float32
#define MBITS_WORDS ((size_t)BATCH * NQ * NK / 32)
__device__ __align__(16) uint32_t g_mbits[MBITS_WORDS];

// ---------------------------------------------------------------------------
// K1 smem: 2 bufs x 4 tensors (Qh,Ql,Kh,Kl), each 128 rows x 32 bf16, row
// stride 80 B. Score staging (128 x 132 f32) overlays the buffers at the end.
// ---------------------------------------------------------------------------
#define K1_CH 10240                        // 128 * 80
#define K1_BUF(b) ((b) * 4 * K1_CH)        // 40960 per buf
#define SMEM_K1 81920
#define SCSTRIDE 132

// ---------------------------------------------------------------------------
// K2 smem: E fp16 chunk (128 x 32, stride 80 B) x2 bufs at 0; V fp16 chunk
// (32 x 128 h+l, stride 272 B) x2 bufs at 20480; rd[128] at 67584.
// Ctx staging (128 x 132 f32 = 67584) overlays the buffers at the end.
// ---------------------------------------------------------------------------
#define K2_E(b) ((b) * 10240)              // 128*80
#define K2_V(b) (20480 + (b) * 17408)      // vh 8704 + vl 8704
#define K2_OFF_RD 67584
#define SMEM_K2 68096
#define K2_SCSTRIDE 132

// ---------------------------------------------------------------------------
// PTX primitives (portable, base sm_103 target)
// ---------------------------------------------------------------------------
__device__ __forceinline__ uint32_t smem_u32(const void* p) {
    uint32_t a;
    asm("{ .reg .u64 t; cvta.to.shared.u64 t, %1; cvt.u32.u64 %0, t; }" : "=r"(a) : "l"(p));
    return a;
}
__device__ __forceinline__ void ldsm_x4(uint32_t a, uint32_t r[4]) {
    asm volatile("ldmatrix.sync.aligned.m8n8.x4.shared.b16 {%0,%1,%2,%3}, [%4];"
        : "=r"(r[0]), "=r"(r[1]), "=r"(r[2]), "=r"(r[3]) : "r"(a));
}
__device__ __forceinline__ void ldsm_x2(uint32_t a, uint32_t r[2]) {
    asm volatile("ldmatrix.sync.aligned.m8n8.x2.shared.b16 {%0,%1}, [%2];"
        : "=r"(r[0]), "=r"(r[1]) : "r"(a));
}
__device__ __forceinline__ void ldsm_x4t(uint32_t a, uint32_t r[4]) {
    asm volatile("ldmatrix.sync.aligned.m8n8.x4.trans.shared.b16 {%0,%1,%2,%3}, [%4];"
        : "=r"(r[0]), "=r"(r[1]), "=r"(r[2]), "=r"(r[3]) : "r"(a));
}
__device__ __forceinline__ void mma16816(float c[4], const uint32_t a[4], uint32_t b0, uint32_t b1) {
    asm volatile("mma.sync.aligned.m16n8k16.row.col.f32.bf16.bf16.f32 "
        "{%0,%1,%2,%3}, {%4,%5,%6,%7}, {%8,%9}, {%0,%1,%2,%3};"
        : "+f"(c[0]), "+f"(c[1]), "+f"(c[2]), "+f"(c[3])
        : "r"(a[0]), "r"(a[1]), "r"(a[2]), "r"(a[3]), "r"(b0), "r"(b1));
}
__device__ __forceinline__ void mma16816h(float c[4], const uint32_t a[4], uint32_t b0, uint32_t b1) {
    asm volatile("mma.sync.aligned.m16n8k16.row.col.f32.f16.f16.f32 "
        "{%0,%1,%2,%3}, {%4,%5,%6,%7}, {%8,%9}, {%0,%1,%2,%3};"
        : "+f"(c[0]), "+f"(c[1]), "+f"(c[2]), "+f"(c[3])
        : "r"(a[0]), "r"(a[1]), "r"(a[2]), "r"(a[3]), "r"(b0), "r"(b1));
}
__device__ __forceinline__ void cp16(uint32_t dst, const void* src) {
    asm volatile("cp.async.cg.shared.global [%0], [%1], 16;" :: "r"(dst), "l"(src));
}
#define CP_COMMIT() asm volatile("cp.async.commit_group;")
#define CP_WAIT1()  asm volatile("cp.async.wait_group 1;")
#define CP_WAIT0()  asm volatile("cp.async.wait_group 0;")

__device__ __forceinline__ uint32_t pack2(__nv_bfloat16 a, __nv_bfloat16 b) {
    __nv_bfloat162 t = __halves2bfloat162(a, b);
    return *reinterpret_cast<uint32_t*>(&t);
}
__device__ __forceinline__ void split2(float x, float y, uint32_t& h, uint32_t& l) {
    __nv_bfloat16 hx = __float2bfloat16(x), hy = __float2bfloat16(y);
    __nv_bfloat16 lx = __float2bfloat16(x - __bfloat162float(hx));
    __nv_bfloat16 ly = __float2bfloat16(y - __bfloat162float(hy));
    h = pack2(hx, hy);
    l = pack2(lx, ly);
}
__device__ __forceinline__ uint32_t pack2h(__half a, __half b) {
    __half2 t = __halves2half2(a, b);
    return *reinterpret_cast<uint32_t*>(&t);
}
__device__ __forceinline__ void split2h(float x, float y, uint32_t& h, uint32_t& l) {
    __half hx = __float2half_rn(x), hy = __float2half_rn(y);
    __half lx = __float2half_rn(x - __half2float(hx));
    __half ly = __float2half_rn(y - __half2float(hy));
    h = pack2h(hx, hy);
    l = pack2h(lx, ly);
}

// ---------------------------------------------------------------------------
__global__ void detect_mask_kernel(const unsigned char* __restrict__ m)
{
    const int tid = threadIdx.x;
    int mis = 0, ftail = 0;
    for (int i = tid * 16; i < tid * 16 + 16; i++) {
        const unsigned char b = m[i];
        if (b) {
            const int r = i & 3;
            if (r == 1) mis = 1;
            else if (r == 2) { if (b != 0x80) mis = 1; else ftail = 1; }
            else if (r == 3) { if (b != 0x3F) mis = 1; else ftail = 1; }
        }
    }
    const int anyMis = __syncthreads_or(mis);
    const int anyF   = __syncthreads_or(ftail);
    if (tid == 0) g_mask_mode = anyMis ? 0 : (anyF ? 2 : 1);
}

__global__ __launch_bounds__(256) void pack_mask_kernel(const void* __restrict__ mask)
{
    const size_t w = (size_t)blockIdx.x * 256 + threadIdx.x;
    const int mode = g_mask_mode;
    uint32_t bits = 0;
    if (mode == 0) {
        const uint4* p = (const uint4*)((const unsigned char*)mask + w * 32);
#pragma unroll
        for (int i = 0; i < 2; i++) {
            const uint4 v = p[i];
            const uint32_t ws[4] = {v.x, v.y, v.z, v.w};
#pragma unroll
            for (int k = 0; k < 4; k++)
#pragma unroll
                for (int byt = 0; byt < 4; byt++)
                    bits |= (uint32_t)(((ws[k] >> (8 * byt)) & 0xffu) != 0u) << (i * 16 + k * 4 + byt);
        }
    } else {
        const uint4* p = (const uint4*)((const uint32_t*)mask + w * 32);
#pragma unroll
        for (int i = 0; i < 8; i++) {
            const uint4 v = p[i];
            bits |= (uint32_t)(v.x != 0u) << (i * 4 + 0);
            bits |= (uint32_t)(v.y != 0u) << (i * 4 + 1);
            bits |= (uint32_t)(v.z != 0u) << (i * 4 + 2);
            bits |= (uint32_t)(v.w != 0u) << (i * 4 + 3);
        }
    }
    g_mbits[w] = bits;
}

__global__ __launch_bounds__(256) void prep_kernel(
    const float* __restrict__ q, const float* __restrict__ k, const float* __restrict__ v)
{
    const size_t t = (size_t)blockIdx.x * 256 + threadIdx.x;   // float4 index
    if (blockIdx.y == 2) {                 // V -> fp16 hi/lo
        const float4 x = ((const float4*)v)[t];
        uint32_t h01, l01, h23, l23;
        split2h(x.x, x.y, h01, l01);
        split2h(x.z, x.w, h23, l23);
        ((uint2*)g_vh)[t] = make_uint2(h01, h23);
        ((uint2*)g_vl)[t] = make_uint2(l01, l23);
        return;
    }
    const float* src = (blockIdx.y == 0) ? q : k;
    __nv_bfloat16* dh = (blockIdx.y == 0) ? g_qh : g_kh;
    __nv_bfloat16* dl = (blockIdx.y == 0) ? g_ql : g_kl;
    const float4 x = ((const float4*)src)[t];
    uint32_t h01, l01, h23, l23;
    split2(x.x, x.y, h01, l01);
    split2(x.z, x.w, h23, l23);
    ((uint2*)dh)[t] = make_uint2(h01, h23);
    ((uint2*)dl)[t] = make_uint2(l01, l23);
}

// ---------------------------------------------------------------------------
// K1: E = exp(mask ? -inf : QK^T * inv) -> fp16 g_e + partial row sums.
// D streamed in 4 chunks of 32, cp.async double-buffered (R9 structure).
// ---------------------------------------------------------------------------
__device__ __forceinline__ void k1_issue(uint32_t sb, int b, int q0, int k0, int ic, int buf, int tid)
{
    const int d0 = ic * 32;
#pragma unroll
    for (int i = 0; i < 8; i++) {
        const int idx = i * 256 + tid;     // 0..2047
        const int t = idx >> 9;            // tensor 0..3
        const int r = (idx >> 2) & 127;
        const int c = idx & 3;
        const __nv_bfloat16* base = (t == 0) ? g_qh : (t == 1) ? g_ql : (t == 2) ? g_kh : g_kl;
        const int row0 = (t < 2) ? q0 : k0;
        cp16(sb + K1_BUF(buf) + t * K1_CH + r * 80 + c * 16,
             base + ((size_t)(b * NQ + row0 + r)) * DHEAD + d0 + c * 8);
    }
}

__global__ __launch_bounds__(256, 2)
void qk_exp_kernel()
{
    extern __shared__ char smem[];
    const uint32_t sb = smem_u32(smem);
    const int tid = threadIdx.x;
    const int wid = tid >> 5;
    const int lane = tid & 31;
    const int wm = wid & 1;     // 64-row half
    const int wn = wid >> 1;    // 32-col group

    const int b  = blockIdx.z;
    const int q0 = blockIdx.y * 128;
    const int k0 = blockIdx.x * 128;

    k1_issue(sb, b, q0, k0, 0, 0, tid); CP_COMMIT();
    k1_issue(sb, b, q0, k0, 1, 1, tid); CP_COMMIT();

    float acc[4][4][4];
#pragma unroll
    for (int mt = 0; mt < 4; mt++)
#pragma unroll
        for (int nt = 0; nt < 4; nt++)
#pragma unroll
            for (int r = 0; r < 4; r++) acc[mt][nt][r] = 0.0f;

    const int lm = lane & 15, lq = lane >> 4;
    const int bn = lane & 7,  bk = (lane >> 3) & 1;

    for (int ic = 0; ic < 4; ic++) {
        const int buf = ic & 1;
        if (ic < 3) { CP_WAIT1(); } else { CP_WAIT0(); }
        __syncthreads();

        const uint32_t qb = sb + K1_BUF(buf);
        const uint32_t kb = sb + K1_BUF(buf) + 2 * K1_CH;
#pragma unroll
        for (int ks = 0; ks < 2; ks++) {
            uint32_t ah[4][4], al[4][4], bh[4][2], bl[4][2];
#pragma unroll
            for (int mt = 0; mt < 4; mt++) {
                const uint32_t a = qb + (wm * 64 + mt * 16 + lm) * 80 + (ks * 16 + lq * 8) * 2;
                ldsm_x4(a, ah[mt]);
                ldsm_x4(a + K1_CH, al[mt]);
            }
#pragma unroll
            for (int nt = 0; nt < 4; nt++) {
                const uint32_t a = kb + (wn * 32 + nt * 8 + bn) * 80 + (ks * 16 + bk * 8) * 2;
                ldsm_x2(a, bh[nt]);
                ldsm_x2(a + K1_CH, bl[nt]);
            }
#pragma unroll
            for (int mt = 0; mt < 4; mt++)
#pragma unroll
                for (int nt = 0; nt < 4; nt++) {
                    mma16816(acc[mt][nt], ah[mt], bh[nt][0], bh[nt][1]);
                    mma16816(acc[mt][nt], ah[mt], bl[nt][0], bl[nt][1]);
                    mma16816(acc[mt][nt], al[mt], bh[nt][0], bh[nt][1]);
                }
        }
        __syncthreads();
        if (ic + 2 < 4) { k1_issue(sb, b, q0, k0, ic + 2, (ic + 2) & 1, tid); CP_COMMIT(); }
    }

    // Stage scores through smem (overlays buffers; all loads consumed).
    float* sc = (float*)smem;
    {
        const int r0 = lane >> 2;
        const int c0 = (lane & 3) * 2;
#pragma unroll
        for (int mt = 0; mt < 4; mt++)
#pragma unroll
            for (int nt = 0; nt < 4; nt++) {
                const int rr = wm * 64 + mt * 16 + r0;
                const int cc = wn * 32 + nt * 8 + c0;
                sc[rr * SCSTRIDE + cc]           = acc[mt][nt][0];
                sc[rr * SCSTRIDE + cc + 1]       = acc[mt][nt][1];
                sc[(rr + 8) * SCSTRIDE + cc]     = acc[mt][nt][2];
                sc[(rr + 8) * SCSTRIDE + cc + 1] = acc[mt][nt][3];
            }
    }
    __syncthreads();

    {
        const int row  = tid & 127;
        const int half = tid >> 7;
        const size_t roff = ((size_t)b * NQ + q0 + row) * NK + k0 + half * 64;
        const uint2 mb = *(const uint2*)(g_mbits +
            ((size_t)b * NQ + q0 + row) * (NK / 32) + (k0 >> 5) + half * 2);
        float rsum = 0.0f;
#pragma unroll
        for (int j = 0; j < 16; j++) {
            const float4 s4 = *(const float4*)&sc[row * SCSTRIDE + half * 64 + j * 4];
            const uint32_t w = (j < 8) ? mb.x : mb.y;
            const int sh = (j & 7) * 4;
            float e[4];
            const float ss[4] = {s4.x, s4.y, s4.z, s4.w};
#pragma unroll
            for (int jj = 0; jj < 4; jj++)
                e[jj] = ((w >> (sh + jj)) & 1u) ? 0.0f : __expf(ss[jj] * INV_SQRT_SCALE);
            // Round to fp16; accumulate row sum from the ROUNDED values so
            // softmax rows stay exactly self-consistent.
            const __half2 p01 = __floats2half2_rn(e[0], e[1]);
            const __half2 p23 = __floats2half2_rn(e[2], e[3]);
            rsum += (__low2float(p01) + __high2float(p01)) +
                    (__low2float(p23) + __high2float(p23));
            union { __half2 h2[2]; uint2 u; } pk;
            pk.h2[0] = p01; pk.h2[1] = p23;
            *(uint2*)(g_e + roff + j * 4) = pk.u;
        }
        sc[row * SCSTRIDE + 128 + half] = rsum;
    }
    __syncthreads();
    if (tid < 128)
        g_partial[((size_t)b * NQ + q0 + tid) * KBLOCKS + blockIdx.x] =
            sc[tid * SCSTRIDE + 128] + sc[tid * SCSTRIDE + 129];
}

// ---------------------------------------------------------------------------
// K2: att = E * rd (fp32 out); ctx = (E @ (Vh+Vl)) * rd via 2-term fp16 MMA.
// NK streamed in 32-key chunks, cp.async double-buffered.
// ---------------------------------------------------------------------------
__device__ __forceinline__ void k2_issue(uint32_t sb, const __half* ebase, int b, int ic, int buf, int tid)
{
    const int n0 = ic * 32;
#pragma unroll
    for (int i = 0; i < 6; i++) {
        const int idx = i * 256 + tid;     // 0..1535
        if (idx < 512) {                   // E fp16 chunk: 128 rows x 4 c16
            const int r = idx >> 2;
            const int c = idx & 3;
            cp16(sb + K2_E(buf) + r * 80 + c * 16,
                 ebase + (size_t)r * NK + n0 + c * 8);
        } else {                           // V h/l: 32 rows x 16 c16 each
            const int j = idx - 512;
            const int h = j >> 9;
            const int r = (j >> 4) & 31;
            const int c = j & 15;
            const __half* base = h ? g_vl : g_vh;
            cp16(sb + K2_V(buf) + h * 8704 + r * 272 + c * 16,
                 base + ((size_t)(b * NK + n0 + r)) * DHEAD + c * 8);
        }
    }
}

__global__ __launch_bounds__(256, 2)
void av_kernel(float* __restrict__ att, float* __restrict__ ctx)
{
    extern __shared__ char smem[];
    const uint32_t sb = smem_u32(smem);
    float* rd = (float*)(smem + K2_OFF_RD);
    const int tid = threadIdx.x;
    const int wid = tid >> 5;
    const int lane = tid & 31;
    const int wm = wid & 1;
    const int wn = wid >> 1;

    const int b  = blockIdx.y;
    const int q0 = blockIdx.x * 128;

    if (tid < 128) {
        const float* p = &g_partial[((size_t)b * NQ + q0 + tid) * KBLOCKS];
        float s = 0.0f;
#pragma unroll
        for (int i = 0; i < KBLOCKS; i++) s += p[i];
        rd[tid] = 1.0f / s;
    }

    const __half* ebase = g_e + ((size_t)b * NQ + q0) * NK;
    float* attbase = att + ((size_t)b * NQ + q0) * NK;
    k2_issue(sb, ebase, b, 0, 0, tid); CP_COMMIT();
    k2_issue(sb, ebase, b, 1, 1, tid); CP_COMMIT();
    __syncthreads();   // rd[] visible to all threads before mainloop reads it

    float acc[4][4][4];
#pragma unroll
    for (int mt = 0; mt < 4; mt++)
#pragma unroll
        for (int nt = 0; nt < 4; nt++)
#pragma unroll
            for (int r = 0; r < 4; r++) acc[mt][nt][r] = 0.0f;

    const int lm = lane & 15, lq = lane >> 4;

    for (int ic = 0; ic < NK / 32; ic++) {
        const int buf = ic & 1;
        const int n0 = ic * 32;
        if (ic < NK / 32 - 1) { CP_WAIT1(); } else { CP_WAIT0(); }
        __syncthreads();

        // ---- MMA: ctx += E @ (Vh + Vl), 2-term fp16 ----
        const uint32_t vb = sb + K2_V(buf);
#pragma unroll
        for (int ks = 0; ks < 2; ks++) {
            uint32_t eh[4][4];
#pragma unroll
            for (int mt = 0; mt < 4; mt++) {
                const uint32_t a = sb + K2_E(buf) + (wm * 64 + mt * 16 + lm) * 80
                                 + (ks * 16 + lq * 8) * 2;
                ldsm_x4(a, eh[mt]);
            }
#pragma unroll
            for (int ntp = 0; ntp < 2; ntp++) {
                uint32_t vh4[4], vl4[4];
                const uint32_t a = vb + (ks * 16 + lm) * 272 + (wn * 32 + ntp * 16 + lq * 8) * 2;
                ldsm_x4t(a, vh4);
                ldsm_x4t(a + 8704, vl4);
#pragma unroll
                for (int mt = 0; mt < 4; mt++) {
                    mma16816h(acc[mt][ntp * 2],     eh[mt], vh4[0], vh4[1]);
                    mma16816h(acc[mt][ntp * 2 + 1], eh[mt], vh4[2], vh4[3]);
                }
#pragma unroll
                for (int mt = 0; mt < 4; mt++) {
                    mma16816h(acc[mt][ntp * 2],     eh[mt], vl4[0], vl4[1]);
                    mma16816h(acc[mt][ntp * 2 + 1], eh[mt], vl4[2], vl4[3]);
                }
            }
        }

        // ---- att output: att = E * rd (reads E smem chunk, writes fp32) ----
        {
            const int r = tid >> 1;            // 0..127
            const int half = tid & 1;          // 16-col half
            const float rr = rd[r];
            float* o = attbase + (size_t)r * NK + n0 + half * 16;
#pragma unroll
            for (int q8 = 0; q8 < 2; q8++) {
                const uint4 ev = *(const uint4*)(smem + K2_E(buf) + r * 80 + half * 32 + q8 * 16);
                const __half2* hp = (const __half2*)&ev;
#pragma unroll
                for (int j = 0; j < 4; j++) {
                    const __half2 h2 = hp[j];
                    *(float2*)(o + q8 * 8 + j * 2) =
                        make_float2(__low2float(h2) * rr, __high2float(h2) * rr);
                }
            }
        }
        __syncthreads();
        if (ic + 2 < NK / 32) { k2_issue(sb, ebase, b, ic + 2, (ic + 2) & 1, tid); CP_COMMIT(); }
    }

    // rd values are needed after the staging overlays smem: keep in register.
    const int row_a = tid & 127;
    const float rr_a = rd[row_a];
    __syncthreads();

    // Stage ctx through smem for coalesced writes (overlays buffers).
    float* sc = (float*)smem;
    {
        const int r0 = lane >> 2;
        const int c0 = (lane & 3) * 2;
#pragma unroll
        for (int mt = 0; mt < 4; mt++)
#pragma unroll
            for (int nt = 0; nt < 4; nt++) {
                const int rr = wm * 64 + mt * 16 + r0;
                const int cc = wn * 32 + nt * 8 + c0;
                sc[rr * K2_SCSTRIDE + cc]           = acc[mt][nt][0];
                sc[rr * K2_SCSTRIDE + cc + 1]       = acc[mt][nt][1];
                sc[(rr + 8) * K2_SCSTRIDE + cc]     = acc[mt][nt][2];
                sc[(rr + 8) * K2_SCSTRIDE + cc + 1] = acc[mt][nt][3];
            }
    }
    __syncthreads();
    {
        const int half = tid >> 7;
        float* o = ctx + ((size_t)b * NQ + q0 + row_a) * DHEAD + half * 64;
#pragma unroll
        for (int j = 0; j < 16; j++) {
            const float4 c4 = *(const float4*)&sc[row_a * K2_SCSTRIDE + half * 64 + j * 4];
            *(float4*)(o + j * 4) = make_float4(c4.x * rr_a, c4.y * rr_a, c4.z * rr_a, c4.w * rr_a);
        }
    }
}

// ---------------------------------------------------------------------------
extern "C" void kernel_launch(void* const* d_in, const int* in_sizes, int n_in,
                              void* d_out, int out_size)
{
    const float* q = (const float*)d_in[0];
    const float* k = (const float*)d_in[1];
    const float* v = (const float*)d_in[2];
    const void*  mask = d_in[3];

    float* out = (float*)d_out;
    float* ctx = out;                                   // [B, NQ, D]
    float* att = out + (size_t)BATCH * NQ * DHEAD;      // [B, NQ, NK]

    cudaFuncSetAttribute(qk_exp_kernel, cudaFuncAttributeMaxDynamicSharedMemorySize, SMEM_K1);
    cudaFuncSetAttribute(av_kernel,     cudaFuncAttributeMaxDynamicSharedMemorySize, SMEM_K2);

    detect_mask_kernel<<<1, 256>>>((const unsigned char*)mask);
    pack_mask_kernel<<<(int)(MBITS_WORDS / 256), 256>>>(mask);
    prep_kernel<<<dim3(4096, 3), 256>>>(q, k, v);

    dim3 g1(NK / 128, NQ / 128, BATCH);
    qk_exp_kernel<<<g1, 256, SMEM_K1>>>();

    dim3 g2(NQ / 128, BATCH);
    av_kernel<<<g2, 256, SMEM_K2>>>(att, ctx);
}

// round 15
// speedup vs baseline: 1.7125x; 1.1377x over previous
// ---------------------------------------------------------------------------
// R15 = R14 (fp16-E pipeline) with two fixes:
//  1. K2 att store re-coalesced (float4, 8 threads per row) - fixes the R14
//     regression (+~50us from scattered float2 stores of 268 MB).
//  2. K1 K-fragments via ldsm_x4 pairs (R10-verified mapping) - ~17% fewer
//     LDSM instructions in the LDS-bound kernel.
// Prediction: 508 -> ~430-445 us (K1 ~205, K2 ~145); rel_err ~2.1e-4.
// ---------------------------------------------------------------------------
#include <cuda_runtime.h>
#include <cuda_bf16.h>
#include <cuda_fp16.h>
#include <cstdint>

#define BATCH 16
#define NQ 2048
#define NK 2048
#define DHEAD 128
#define KBLOCKS 16
#define INV_SQRT_SCALE 0.08838834764831845f  // 1/sqrt(128)

// ---------------------------------------------------------------------------
// Global scratch: bf16 hi/lo Q,K; fp16 hi/lo V; fp16 unnormalized E; bit mask.
// ---------------------------------------------------------------------------
#define TENSOR_ELEMS ((size_t)BATCH * NQ * DHEAD)
__device__ __align__(16) __nv_bfloat16 g_qh[TENSOR_ELEMS];
__device__ __align__(16) __nv_bfloat16 g_ql[TENSOR_ELEMS];
__device__ __align__(16) __nv_bfloat16 g_kh[TENSOR_ELEMS];
__device__ __align__(16) __nv_bfloat16 g_kl[TENSOR_ELEMS];
__device__ __align__(16) __half g_vh[TENSOR_ELEMS];
__device__ __align__(16) __half g_vl[TENSOR_ELEMS];
__device__ __align__(16) __half g_e[(size_t)BATCH * NQ * NK];   // 134 MB
__device__ float g_partial[(size_t)BATCH * NQ * KBLOCKS];
__device__ int g_mask_mode;   // 0 = bytes, 1 = int32, 2 = float32
#define MBITS_WORDS ((size_t)BATCH * NQ * NK / 32)
__device__ __align__(16) uint32_t g_mbits[MBITS_WORDS];

// ---------------------------------------------------------------------------
// K1 smem: 2 bufs x 4 tensors (Qh,Ql,Kh,Kl), each 128 rows x 32 bf16, row
// stride 80 B. Score staging (128 x 132 f32) overlays the buffers at the end.
// ---------------------------------------------------------------------------
#define K1_CH 10240                        // 128 * 80
#define K1_BUF(b) ((b) * 4 * K1_CH)        // 40960 per buf
#define SMEM_K1 81920
#define SCSTRIDE 132

// ---------------------------------------------------------------------------
// K2 smem: E fp16 chunk (128 x 32, stride 80 B) x2 bufs at 0; V fp16 chunk
// (32 x 128 h+l, stride 272 B) x2 bufs at 20480; rd[128] at 67584.
// Ctx staging (128 x 132 f32 = 67584) overlays the buffers at the end.
// ---------------------------------------------------------------------------
#define K2_E(b) ((b) * 10240)              // 128*80
#define K2_V(b) (20480 + (b) * 17408)      // vh 8704 + vl 8704
#define K2_OFF_RD 67584
#define SMEM_K2 68096
#define K2_SCSTRIDE 132

// ---------------------------------------------------------------------------
// PTX primitives (portable, base sm_103 target)
// ---------------------------------------------------------------------------
__device__ __forceinline__ uint32_t smem_u32(const void* p) {
    uint32_t a;
    asm("{ .reg .u64 t; cvta.to.shared.u64 t, %1; cvt.u32.u64 %0, t; }" : "=r"(a) : "l"(p));
    return a;
}
__device__ __forceinline__ void ldsm_x4(uint32_t a, uint32_t r[4]) {
    asm volatile("ldmatrix.sync.aligned.m8n8.x4.shared.b16 {%0,%1,%2,%3}, [%4];"
        : "=r"(r[0]), "=r"(r[1]), "=r"(r[2]), "=r"(r[3]) : "r"(a));
}
__device__ __forceinline__ void ldsm_x4t(uint32_t a, uint32_t r[4]) {
    asm volatile("ldmatrix.sync.aligned.m8n8.x4.trans.shared.b16 {%0,%1,%2,%3}, [%4];"
        : "=r"(r[0]), "=r"(r[1]), "=r"(r[2]), "=r"(r[3]) : "r"(a));
}
__device__ __forceinline__ void mma16816(float c[4], const uint32_t a[4], uint32_t b0, uint32_t b1) {
    asm volatile("mma.sync.aligned.m16n8k16.row.col.f32.bf16.bf16.f32 "
        "{%0,%1,%2,%3}, {%4,%5,%6,%7}, {%8,%9}, {%0,%1,%2,%3};"
        : "+f"(c[0]), "+f"(c[1]), "+f"(c[2]), "+f"(c[3])
        : "r"(a[0]), "r"(a[1]), "r"(a[2]), "r"(a[3]), "r"(b0), "r"(b1));
}
__device__ __forceinline__ void mma16816h(float c[4], const uint32_t a[4], uint32_t b0, uint32_t b1) {
    asm volatile("mma.sync.aligned.m16n8k16.row.col.f32.f16.f16.f32 "
        "{%0,%1,%2,%3}, {%4,%5,%6,%7}, {%8,%9}, {%0,%1,%2,%3};"
        : "+f"(c[0]), "+f"(c[1]), "+f"(c[2]), "+f"(c[3])
        : "r"(a[0]), "r"(a[1]), "r"(a[2]), "r"(a[3]), "r"(b0), "r"(b1));
}
__device__ __forceinline__ void cp16(uint32_t dst, const void* src) {
    asm volatile("cp.async.cg.shared.global [%0], [%1], 16;" :: "r"(dst), "l"(src));
}
#define CP_COMMIT() asm volatile("cp.async.commit_group;")
#define CP_WAIT1()  asm volatile("cp.async.wait_group 1;")
#define CP_WAIT0()  asm volatile("cp.async.wait_group 0;")

__device__ __forceinline__ uint32_t pack2(__nv_bfloat16 a, __nv_bfloat16 b) {
    __nv_bfloat162 t = __halves2bfloat162(a, b);
    return *reinterpret_cast<uint32_t*>(&t);
}
__device__ __forceinline__ void split2(float x, float y, uint32_t& h, uint32_t& l) {
    __nv_bfloat16 hx = __float2bfloat16(x), hy = __float2bfloat16(y);
    __nv_bfloat16 lx = __float2bfloat16(x - __bfloat162float(hx));
    __nv_bfloat16 ly = __float2bfloat16(y - __bfloat162float(hy));
    h = pack2(hx, hy);
    l = pack2(lx, ly);
}
__device__ __forceinline__ uint32_t pack2h(__half a, __half b) {
    __half2 t = __halves2half2(a, b);
    return *reinterpret_cast<uint32_t*>(&t);
}
__device__ __forceinline__ void split2h(float x, float y, uint32_t& h, uint32_t& l) {
    __half hx = __float2half_rn(x), hy = __float2half_rn(y);
    __half lx = __float2half_rn(x - __half2float(hx));
    __half ly = __float2half_rn(y - __half2float(hy));
    h = pack2h(hx, hy);
    l = pack2h(lx, ly);
}

// ---------------------------------------------------------------------------
__global__ void detect_mask_kernel(const unsigned char* __restrict__ m)
{
    const int tid = threadIdx.x;
    int mis = 0, ftail = 0;
    for (int i = tid * 16; i < tid * 16 + 16; i++) {
        const unsigned char b = m[i];
        if (b) {
            const int r = i & 3;
            if (r == 1) mis = 1;
            else if (r == 2) { if (b != 0x80) mis = 1; else ftail = 1; }
            else if (r == 3) { if (b != 0x3F) mis = 1; else ftail = 1; }
        }
    }
    const int anyMis = __syncthreads_or(mis);
    const int anyF   = __syncthreads_or(ftail);
    if (tid == 0) g_mask_mode = anyMis ? 0 : (anyF ? 2 : 1);
}

__global__ __launch_bounds__(256) void pack_mask_kernel(const void* __restrict__ mask)
{
    const size_t w = (size_t)blockIdx.x * 256 + threadIdx.x;
    const int mode = g_mask_mode;
    uint32_t bits = 0;
    if (mode == 0) {
        const uint4* p = (const uint4*)((const unsigned char*)mask + w * 32);
#pragma unroll
        for (int i = 0; i < 2; i++) {
            const uint4 v = p[i];
            const uint32_t ws[4] = {v.x, v.y, v.z, v.w};
#pragma unroll
            for (int k = 0; k < 4; k++)
#pragma unroll
                for (int byt = 0; byt < 4; byt++)
                    bits |= (uint32_t)(((ws[k] >> (8 * byt)) & 0xffu) != 0u) << (i * 16 + k * 4 + byt);
        }
    } else {
        const uint4* p = (const uint4*)((const uint32_t*)mask + w * 32);
#pragma unroll
        for (int i = 0; i < 8; i++) {
            const uint4 v = p[i];
            bits |= (uint32_t)(v.x != 0u) << (i * 4 + 0);
            bits |= (uint32_t)(v.y != 0u) << (i * 4 + 1);
            bits |= (uint32_t)(v.z != 0u) << (i * 4 + 2);
            bits |= (uint32_t)(v.w != 0u) << (i * 4 + 3);
        }
    }
    g_mbits[w] = bits;
}

__global__ __launch_bounds__(256) void prep_kernel(
    const float* __restrict__ q, const float* __restrict__ k, const float* __restrict__ v)
{
    const size_t t = (size_t)blockIdx.x * 256 + threadIdx.x;   // float4 index
    if (blockIdx.y == 2) {                 // V -> fp16 hi/lo
        const float4 x = ((const float4*)v)[t];
        uint32_t h01, l01, h23, l23;
        split2h(x.x, x.y, h01, l01);
        split2h(x.z, x.w, h23, l23);
        ((uint2*)g_vh)[t] = make_uint2(h01, h23);
        ((uint2*)g_vl)[t] = make_uint2(l01, l23);
        return;
    }
    const float* src = (blockIdx.y == 0) ? q : k;
    __nv_bfloat16* dh = (blockIdx.y == 0) ? g_qh : g_kh;
    __nv_bfloat16* dl = (blockIdx.y == 0) ? g_ql : g_kl;
    const float4 x = ((const float4*)src)[t];
    uint32_t h01, l01, h23, l23;
    split2(x.x, x.y, h01, l01);
    split2(x.z, x.w, h23, l23);
    ((uint2*)dh)[t] = make_uint2(h01, h23);
    ((uint2*)dl)[t] = make_uint2(l01, l23);
}

// ---------------------------------------------------------------------------
// K1: E = exp(mask ? -inf : QK^T * inv) -> fp16 g_e + partial row sums.
// D streamed in 4 chunks of 32, cp.async double-buffered.
// ---------------------------------------------------------------------------
__device__ __forceinline__ void k1_issue(uint32_t sb, int b, int q0, int k0, int ic, int buf, int tid)
{
    const int d0 = ic * 32;
#pragma unroll
    for (int i = 0; i < 8; i++) {
        const int idx = i * 256 + tid;     // 0..2047
        const int t = idx >> 9;            // tensor 0..3
        const int r = (idx >> 2) & 127;
        const int c = idx & 3;
        const __nv_bfloat16* base = (t == 0) ? g_qh : (t == 1) ? g_ql : (t == 2) ? g_kh : g_kl;
        const int row0 = (t < 2) ? q0 : k0;
        cp16(sb + K1_BUF(buf) + t * K1_CH + r * 80 + c * 16,
             base + ((size_t)(b * NQ + row0 + r)) * DHEAD + d0 + c * 8);
    }
}

__global__ __launch_bounds__(256, 2)
void qk_exp_kernel()
{
    extern __shared__ char smem[];
    const uint32_t sb = smem_u32(smem);
    const int tid = threadIdx.x;
    const int wid = tid >> 5;
    const int lane = tid & 31;
    const int wm = wid & 1;     // 64-row half
    const int wn = wid >> 1;    // 32-col group

    const int b  = blockIdx.z;
    const int q0 = blockIdx.y * 128;
    const int k0 = blockIdx.x * 128;

    k1_issue(sb, b, q0, k0, 0, 0, tid); CP_COMMIT();
    k1_issue(sb, b, q0, k0, 1, 1, tid); CP_COMMIT();

    float acc[4][4][4];
#pragma unroll
    for (int mt = 0; mt < 4; mt++)
#pragma unroll
        for (int nt = 0; nt < 4; nt++)
#pragma unroll
            for (int r = 0; r < 4; r++) acc[mt][nt][r] = 0.0f;

    const int lm = lane & 15, lq = lane >> 4;

    for (int ic = 0; ic < 4; ic++) {
        const int buf = ic & 1;
        if (ic < 3) { CP_WAIT1(); } else { CP_WAIT0(); }
        __syncthreads();

        const uint32_t qb = sb + K1_BUF(buf);
        const uint32_t kb = sb + K1_BUF(buf) + 2 * K1_CH;
#pragma unroll
        for (int ks = 0; ks < 2; ks++) {
            uint32_t ah[4][4], al[4][4], kh[2][4], kl[2][4];
#pragma unroll
            for (int mt = 0; mt < 4; mt++) {
                const uint32_t a = qb + (wm * 64 + mt * 16 + lm) * 80 + (ks * 16 + lq * 8) * 2;
                ldsm_x4(a, ah[mt]);
                ldsm_x4(a + K1_CH, al[mt]);
            }
            // K fragments: 2 ldsm_x4 per hi/lo cover all four n8 groups
            // (R10-verified mapping: group g -> np=g>>1, su=g&1,
            //  b-frags {k[np][su], k[np][su+2]}).
#pragma unroll
            for (int np = 0; np < 2; np++) {
                const uint32_t a = kb + (wn * 32 + np * 16 + lm) * 80 + (ks * 16 + lq * 8) * 2;
                ldsm_x4(a, kh[np]);
                ldsm_x4(a + K1_CH, kl[np]);
            }
#pragma unroll
            for (int mt = 0; mt < 4; mt++)
#pragma unroll
                for (int g = 0; g < 4; g++) {
                    const int np = g >> 1, su = g & 1;
                    mma16816(acc[mt][g], ah[mt], kh[np][su], kh[np][su + 2]);
                    mma16816(acc[mt][g], ah[mt], kl[np][su], kl[np][su + 2]);
                    mma16816(acc[mt][g], al[mt], kh[np][su], kh[np][su + 2]);
                }
        }
        __syncthreads();
        if (ic + 2 < 4) { k1_issue(sb, b, q0, k0, ic + 2, (ic + 2) & 1, tid); CP_COMMIT(); }
    }

    // Stage scores through smem (overlays buffers; all loads consumed).
    float* sc = (float*)smem;
    {
        const int r0 = lane >> 2;
        const int c0 = (lane & 3) * 2;
#pragma unroll
        for (int mt = 0; mt < 4; mt++)
#pragma unroll
            for (int nt = 0; nt < 4; nt++) {
                const int rr = wm * 64 + mt * 16 + r0;
                const int cc = wn * 32 + nt * 8 + c0;
                sc[rr * SCSTRIDE + cc]           = acc[mt][nt][0];
                sc[rr * SCSTRIDE + cc + 1]       = acc[mt][nt][1];
                sc[(rr + 8) * SCSTRIDE + cc]     = acc[mt][nt][2];
                sc[(rr + 8) * SCSTRIDE + cc + 1] = acc[mt][nt][3];
            }
    }
    __syncthreads();

    {
        const int row  = tid & 127;
        const int half = tid >> 7;
        const size_t roff = ((size_t)b * NQ + q0 + row) * NK + k0 + half * 64;
        const uint2 mb = *(const uint2*)(g_mbits +
            ((size_t)b * NQ + q0 + row) * (NK / 32) + (k0 >> 5) + half * 2);
        float rsum = 0.0f;
#pragma unroll
        for (int j = 0; j < 16; j++) {
            const float4 s4 = *(const float4*)&sc[row * SCSTRIDE + half * 64 + j * 4];
            const uint32_t w = (j < 8) ? mb.x : mb.y;
            const int sh = (j & 7) * 4;
            float e[4];
            const float ss[4] = {s4.x, s4.y, s4.z, s4.w};
#pragma unroll
            for (int jj = 0; jj < 4; jj++)
                e[jj] = ((w >> (sh + jj)) & 1u) ? 0.0f : __expf(ss[jj] * INV_SQRT_SCALE);
            // Round to fp16; accumulate row sum from the ROUNDED values so
            // softmax rows stay exactly self-consistent.
            const __half2 p01 = __floats2half2_rn(e[0], e[1]);
            const __half2 p23 = __floats2half2_rn(e[2], e[3]);
            rsum += (__low2float(p01) + __high2float(p01)) +
                    (__low2float(p23) + __high2float(p23));
            union { __half2 h2[2]; uint2 u; } pk;
            pk.h2[0] = p01; pk.h2[1] = p23;
            *(uint2*)(g_e + roff + j * 4) = pk.u;
        }
        sc[row * SCSTRIDE + 128 + half] = rsum;
    }
    __syncthreads();
    if (tid < 128)
        g_partial[((size_t)b * NQ + q0 + tid) * KBLOCKS + blockIdx.x] =
            sc[tid * SCSTRIDE + 128] + sc[tid * SCSTRIDE + 129];
}

// ---------------------------------------------------------------------------
// K2: att = E * rd (fp32 out, coalesced); ctx = (E @ (Vh+Vl)) * rd via
// 2-term fp16 MMA. NK streamed in 32-key chunks, cp.async double-buffered.
// ---------------------------------------------------------------------------
__device__ __forceinline__ void k2_issue(uint32_t sb, const __half* ebase, int b, int ic, int buf, int tid)
{
    const int n0 = ic * 32;
#pragma unroll
    for (int i = 0; i < 6; i++) {
        const int idx = i * 256 + tid;     // 0..1535
        if (idx < 512) {                   // E fp16 chunk: 128 rows x 4 c16
            const int r = idx >> 2;
            const int c = idx & 3;
            cp16(sb + K2_E(buf) + r * 80 + c * 16,
                 ebase + (size_t)r * NK + n0 + c * 8);
        } else {                           // V h/l: 32 rows x 16 c16 each
            const int j = idx - 512;
            const int h = j >> 9;
            const int r = (j >> 4) & 31;
            const int c = j & 15;
            const __half* base = h ? g_vl : g_vh;
            cp16(sb + K2_V(buf) + h * 8704 + r * 272 + c * 16,
                 base + ((size_t)(b * NK + n0 + r)) * DHEAD + c * 8);
        }
    }
}

__global__ __launch_bounds__(256, 2)
void av_kernel(float* __restrict__ att, float* __restrict__ ctx)
{
    extern __shared__ char smem[];
    const uint32_t sb = smem_u32(smem);
    float* rd = (float*)(smem + K2_OFF_RD);
    const int tid = threadIdx.x;
    const int wid = tid >> 5;
    const int lane = tid & 31;
    const int wm = wid & 1;
    const int wn = wid >> 1;

    const int b  = blockIdx.y;
    const int q0 = blockIdx.x * 128;

    if (tid < 128) {
        const float* p = &g_partial[((size_t)b * NQ + q0 + tid) * KBLOCKS];
        float s = 0.0f;
#pragma unroll
        for (int i = 0; i < KBLOCKS; i++) s += p[i];
        rd[tid] = 1.0f / s;
    }

    const __half* ebase = g_e + ((size_t)b * NQ + q0) * NK;
    float* attbase = att + ((size_t)b * NQ + q0) * NK;
    k2_issue(sb, ebase, b, 0, 0, tid); CP_COMMIT();
    k2_issue(sb, ebase, b, 1, 1, tid); CP_COMMIT();
    __syncthreads();   // rd[] visible before the mainloop reads it

    float acc[4][4][4];
#pragma unroll
    for (int mt = 0; mt < 4; mt++)
#pragma unroll
        for (int nt = 0; nt < 4; nt++)
#pragma unroll
            for (int r = 0; r < 4; r++) acc[mt][nt][r] = 0.0f;

    const int lm = lane & 15, lq = lane >> 4;

    for (int ic = 0; ic < NK / 32; ic++) {
        const int buf = ic & 1;
        const int n0 = ic * 32;
        if (ic < NK / 32 - 1) { CP_WAIT1(); } else { CP_WAIT0(); }
        __syncthreads();

        // ---- MMA: ctx += E @ (Vh + Vl), 2-term fp16 ----
        const uint32_t vb = sb + K2_V(buf);
#pragma unroll
        for (int ks = 0; ks < 2; ks++) {
            uint32_t eh[4][4];
#pragma unroll
            for (int mt = 0; mt < 4; mt++) {
                const uint32_t a = sb + K2_E(buf) + (wm * 64 + mt * 16 + lm) * 80
                                 + (ks * 16 + lq * 8) * 2;
                ldsm_x4(a, eh[mt]);
            }
#pragma unroll
            for (int ntp = 0; ntp < 2; ntp++) {
                uint32_t vh4[4], vl4[4];
                const uint32_t a = vb + (ks * 16 + lm) * 272 + (wn * 32 + ntp * 16 + lq * 8) * 2;
                ldsm_x4t(a, vh4);
                ldsm_x4t(a + 8704, vl4);
#pragma unroll
                for (int mt = 0; mt < 4; mt++) {
                    mma16816h(acc[mt][ntp * 2],     eh[mt], vh4[0], vh4[1]);
                    mma16816h(acc[mt][ntp * 2 + 1], eh[mt], vh4[2], vh4[3]);
                }
#pragma unroll
                for (int mt = 0; mt < 4; mt++) {
                    mma16816h(acc[mt][ntp * 2],     eh[mt], vl4[0], vl4[1]);
                    mma16816h(acc[mt][ntp * 2 + 1], eh[mt], vl4[2], vl4[3]);
                }
            }
        }

        // ---- att output: att = E * rd (COALESCED: 8 threads per row) ----
#pragma unroll
        for (int i = 0; i < 4; i++) {
            const int idx = i * 256 + tid;    // 0..1023
            const int r = idx >> 3;           // 0..127
            const int c4 = idx & 7;           // float4 column group
            const uint2 ev = *(const uint2*)(smem + K2_E(buf) + r * 80 + c4 * 8);
            const __half2 h01 = *(const __half2*)&ev.x;
            const __half2 h23 = *(const __half2*)&ev.y;
            const float rr = rd[r];
            *(float4*)(attbase + (size_t)r * NK + n0 + c4 * 4) = make_float4(
                __low2float(h01) * rr, __high2float(h01) * rr,
                __low2float(h23) * rr, __high2float(h23) * rr);
        }
        __syncthreads();
        if (ic + 2 < NK / 32) { k2_issue(sb, ebase, b, ic + 2, (ic + 2) & 1, tid); CP_COMMIT(); }
    }

    // rd values are needed after the staging overlays smem: keep in register.
    const int row_a = tid & 127;
    const float rr_a = rd[row_a];
    __syncthreads();

    // Stage ctx through smem for coalesced writes (overlays buffers).
    float* sc = (float*)smem;
    {
        const int r0 = lane >> 2;
        const int c0 = (lane & 3) * 2;
#pragma unroll
        for (int mt = 0; mt < 4; mt++)
#pragma unroll
            for (int nt = 0; nt < 4; nt++) {
                const int rr = wm * 64 + mt * 16 + r0;
                const int cc = wn * 32 + nt * 8 + c0;
                sc[rr * K2_SCSTRIDE + cc]           = acc[mt][nt][0];
                sc[rr * K2_SCSTRIDE + cc + 1]       = acc[mt][nt][1];
                sc[(rr + 8) * K2_SCSTRIDE + cc]     = acc[mt][nt][2];
                sc[(rr + 8) * K2_SCSTRIDE + cc + 1] = acc[mt][nt][3];
            }
    }
    __syncthreads();
    {
        const int half = tid >> 7;
        float* o = ctx + ((size_t)b * NQ + q0 + row_a) * DHEAD + half * 64;
#pragma unroll
        for (int j = 0; j < 16; j++) {
            const float4 c4 = *(const float4*)&sc[row_a * K2_SCSTRIDE + half * 64 + j * 4];
            *(float4*)(o + j * 4) = make_float4(c4.x * rr_a, c4.y * rr_a, c4.z * rr_a, c4.w * rr_a);
        }
    }
}

// ---------------------------------------------------------------------------
extern "C" void kernel_launch(void* const* d_in, const int* in_sizes, int n_in,
                              void* d_out, int out_size)
{
    const float* q = (const float*)d_in[0];
    const float* k = (const float*)d_in[1];
    const float* v = (const float*)d_in[2];
    const void*  mask = d_in[3];

    float* out = (float*)d_out;
    float* ctx = out;                                   // [B, NQ, D]
    float* att = out + (size_t)BATCH * NQ * DHEAD;      // [B, NQ, NK]

    cudaFuncSetAttribute(qk_exp_kernel, cudaFuncAttributeMaxDynamicSharedMemorySize, SMEM_K1);
    cudaFuncSetAttribute(av_kernel,     cudaFuncAttributeMaxDynamicSharedMemorySize, SMEM_K2);

    detect_mask_kernel<<<1, 256>>>((const unsigned char*)mask);
    pack_mask_kernel<<<(int)(MBITS_WORDS / 256), 256>>>(mask);
    prep_kernel<<<dim3(4096, 3), 256>>>(q, k, v);

    dim3 g1(NK / 128, NQ / 128, BATCH);
    qk_exp_kernel<<<g1, 256, SMEM_K1>>>();

    dim3 g2(NQ / 128, BATCH);
    av_kernel<<<g2, 256, SMEM_K2>>>(att, ctx);
}

// round 16
// speedup vs baseline: 1.7797x; 1.0392x over previous
// ---------------------------------------------------------------------------
// R16 = R15 with K1's K-fragment loads reverted to the R14 ldsm_x2 form
// (measured 219us vs R15's x4 pairing at 234us: the x4 mapping cost more ALU
// than it saved in LDSM). K2 keeps R15's coalesced att store (measured win).
// Micro: epilogue mask uint2 load hoisted above the staging syncs.
// Prediction: K1 ~215, K2 ~138, total 447 -> ~428-435; rel_err 2.06e-4.
// ---------------------------------------------------------------------------
#include <cuda_runtime.h>
#include <cuda_bf16.h>
#include <cuda_fp16.h>
#include <cstdint>

#define BATCH 16
#define NQ 2048
#define NK 2048
#define DHEAD 128
#define KBLOCKS 16
#define INV_SQRT_SCALE 0.08838834764831845f  // 1/sqrt(128)

// ---------------------------------------------------------------------------
// Global scratch: bf16 hi/lo Q,K; fp16 hi/lo V; fp16 unnormalized E; bit mask.
// ---------------------------------------------------------------------------
#define TENSOR_ELEMS ((size_t)BATCH * NQ * DHEAD)
__device__ __align__(16) __nv_bfloat16 g_qh[TENSOR_ELEMS];
__device__ __align__(16) __nv_bfloat16 g_ql[TENSOR_ELEMS];
__device__ __align__(16) __nv_bfloat16 g_kh[TENSOR_ELEMS];
__device__ __align__(16) __nv_bfloat16 g_kl[TENSOR_ELEMS];
__device__ __align__(16) __half g_vh[TENSOR_ELEMS];
__device__ __align__(16) __half g_vl[TENSOR_ELEMS];
__device__ __align__(16) __half g_e[(size_t)BATCH * NQ * NK];   // 134 MB
__device__ float g_partial[(size_t)BATCH * NQ * KBLOCKS];
__device__ int g_mask_mode;   // 0 = bytes, 1 = int32, 2 = float32
#define MBITS_WORDS ((size_t)BATCH * NQ * NK / 32)
__device__ __align__(16) uint32_t g_mbits[MBITS_WORDS];

// ---------------------------------------------------------------------------
// K1 smem: 2 bufs x 4 tensors (Qh,Ql,Kh,Kl), each 128 rows x 32 bf16, row
// stride 80 B. Score staging (128 x 132 f32) overlays the buffers at the end.
// ---------------------------------------------------------------------------
#define K1_CH 10240                        // 128 * 80
#define K1_BUF(b) ((b) * 4 * K1_CH)        // 40960 per buf
#define SMEM_K1 81920
#define SCSTRIDE 132

// ---------------------------------------------------------------------------
// K2 smem: E fp16 chunk (128 x 32, stride 80 B) x2 bufs at 0; V fp16 chunk
// (32 x 128 h+l, stride 272 B) x2 bufs at 20480; rd[128] at 67584.
// Ctx staging (128 x 132 f32 = 67584) overlays the buffers at the end.
// ---------------------------------------------------------------------------
#define K2_E(b) ((b) * 10240)              // 128*80
#define K2_V(b) (20480 + (b) * 17408)      // vh 8704 + vl 8704
#define K2_OFF_RD 67584
#define SMEM_K2 68096
#define K2_SCSTRIDE 132

// ---------------------------------------------------------------------------
// PTX primitives (portable, base sm_103 target)
// ---------------------------------------------------------------------------
__device__ __forceinline__ uint32_t smem_u32(const void* p) {
    uint32_t a;
    asm("{ .reg .u64 t; cvta.to.shared.u64 t, %1; cvt.u32.u64 %0, t; }" : "=r"(a) : "l"(p));
    return a;
}
__device__ __forceinline__ void ldsm_x4(uint32_t a, uint32_t r[4]) {
    asm volatile("ldmatrix.sync.aligned.m8n8.x4.shared.b16 {%0,%1,%2,%3}, [%4];"
        : "=r"(r[0]), "=r"(r[1]), "=r"(r[2]), "=r"(r[3]) : "r"(a));
}
__device__ __forceinline__ void ldsm_x2(uint32_t a, uint32_t r[2]) {
    asm volatile("ldmatrix.sync.aligned.m8n8.x2.shared.b16 {%0,%1}, [%2];"
        : "=r"(r[0]), "=r"(r[1]) : "r"(a));
}
__device__ __forceinline__ void ldsm_x4t(uint32_t a, uint32_t r[4]) {
    asm volatile("ldmatrix.sync.aligned.m8n8.x4.trans.shared.b16 {%0,%1,%2,%3}, [%4];"
        : "=r"(r[0]), "=r"(r[1]), "=r"(r[2]), "=r"(r[3]) : "r"(a));
}
__device__ __forceinline__ void mma16816(float c[4], const uint32_t a[4], uint32_t b0, uint32_t b1) {
    asm volatile("mma.sync.aligned.m16n8k16.row.col.f32.bf16.bf16.f32 "
        "{%0,%1,%2,%3}, {%4,%5,%6,%7}, {%8,%9}, {%0,%1,%2,%3};"
        : "+f"(c[0]), "+f"(c[1]), "+f"(c[2]), "+f"(c[3])
        : "r"(a[0]), "r"(a[1]), "r"(a[2]), "r"(a[3]), "r"(b0), "r"(b1));
}
__device__ __forceinline__ void mma16816h(float c[4], const uint32_t a[4], uint32_t b0, uint32_t b1) {
    asm volatile("mma.sync.aligned.m16n8k16.row.col.f32.f16.f16.f32 "
        "{%0,%1,%2,%3}, {%4,%5,%6,%7}, {%8,%9}, {%0,%1,%2,%3};"
        : "+f"(c[0]), "+f"(c[1]), "+f"(c[2]), "+f"(c[3])
        : "r"(a[0]), "r"(a[1]), "r"(a[2]), "r"(a[3]), "r"(b0), "r"(b1));
}
__device__ __forceinline__ void cp16(uint32_t dst, const void* src) {
    asm volatile("cp.async.cg.shared.global [%0], [%1], 16;" :: "r"(dst), "l"(src));
}
#define CP_COMMIT() asm volatile("cp.async.commit_group;")
#define CP_WAIT1()  asm volatile("cp.async.wait_group 1;")
#define CP_WAIT0()  asm volatile("cp.async.wait_group 0;")

__device__ __forceinline__ uint32_t pack2(__nv_bfloat16 a, __nv_bfloat16 b) {
    __nv_bfloat162 t = __halves2bfloat162(a, b);
    return *reinterpret_cast<uint32_t*>(&t);
}
__device__ __forceinline__ void split2(float x, float y, uint32_t& h, uint32_t& l) {
    __nv_bfloat16 hx = __float2bfloat16(x), hy = __float2bfloat16(y);
    __nv_bfloat16 lx = __float2bfloat16(x - __bfloat162float(hx));
    __nv_bfloat16 ly = __float2bfloat16(y - __bfloat162float(hy));
    h = pack2(hx, hy);
    l = pack2(lx, ly);
}
__device__ __forceinline__ uint32_t pack2h(__half a, __half b) {
    __half2 t = __halves2half2(a, b);
    return *reinterpret_cast<uint32_t*>(&t);
}
__device__ __forceinline__ void split2h(float x, float y, uint32_t& h, uint32_t& l) {
    __half hx = __float2half_rn(x), hy = __float2half_rn(y);
    __half lx = __float2half_rn(x - __half2float(hx));
    __half ly = __float2half_rn(y - __half2float(hy));
    h = pack2h(hx, hy);
    l = pack2h(lx, ly);
}

// ---------------------------------------------------------------------------
__global__ void detect_mask_kernel(const unsigned char* __restrict__ m)
{
    const int tid = threadIdx.x;
    int mis = 0, ftail = 0;
    for (int i = tid * 16; i < tid * 16 + 16; i++) {
        const unsigned char b = m[i];
        if (b) {
            const int r = i & 3;
            if (r == 1) mis = 1;
            else if (r == 2) { if (b != 0x80) mis = 1; else ftail = 1; }
            else if (r == 3) { if (b != 0x3F) mis = 1; else ftail = 1; }
        }
    }
    const int anyMis = __syncthreads_or(mis);
    const int anyF   = __syncthreads_or(ftail);
    if (tid == 0) g_mask_mode = anyMis ? 0 : (anyF ? 2 : 1);
}

__global__ __launch_bounds__(256) void pack_mask_kernel(const void* __restrict__ mask)
{
    const size_t w = (size_t)blockIdx.x * 256 + threadIdx.x;
    const int mode = g_mask_mode;
    uint32_t bits = 0;
    if (mode == 0) {
        const uint4* p = (const uint4*)((const unsigned char*)mask + w * 32);
#pragma unroll
        for (int i = 0; i < 2; i++) {
            const uint4 v = p[i];
            const uint32_t ws[4] = {v.x, v.y, v.z, v.w};
#pragma unroll
            for (int k = 0; k < 4; k++)
#pragma unroll
                for (int byt = 0; byt < 4; byt++)
                    bits |= (uint32_t)(((ws[k] >> (8 * byt)) & 0xffu) != 0u) << (i * 16 + k * 4 + byt);
        }
    } else {
        const uint4* p = (const uint4*)((const uint32_t*)mask + w * 32);
#pragma unroll
        for (int i = 0; i < 8; i++) {
            const uint4 v = p[i];
            bits |= (uint32_t)(v.x != 0u) << (i * 4 + 0);
            bits |= (uint32_t)(v.y != 0u) << (i * 4 + 1);
            bits |= (uint32_t)(v.z != 0u) << (i * 4 + 2);
            bits |= (uint32_t)(v.w != 0u) << (i * 4 + 3);
        }
    }
    g_mbits[w] = bits;
}

__global__ __launch_bounds__(256) void prep_kernel(
    const float* __restrict__ q, const float* __restrict__ k, const float* __restrict__ v)
{
    const size_t t = (size_t)blockIdx.x * 256 + threadIdx.x;   // float4 index
    if (blockIdx.y == 2) {                 // V -> fp16 hi/lo
        const float4 x = ((const float4*)v)[t];
        uint32_t h01, l01, h23, l23;
        split2h(x.x, x.y, h01, l01);
        split2h(x.z, x.w, h23, l23);
        ((uint2*)g_vh)[t] = make_uint2(h01, h23);
        ((uint2*)g_vl)[t] = make_uint2(l01, l23);
        return;
    }
    const float* src = (blockIdx.y == 0) ? q : k;
    __nv_bfloat16* dh = (blockIdx.y == 0) ? g_qh : g_kh;
    __nv_bfloat16* dl = (blockIdx.y == 0) ? g_ql : g_kl;
    const float4 x = ((const float4*)src)[t];
    uint32_t h01, l01, h23, l23;
    split2(x.x, x.y, h01, l01);
    split2(x.z, x.w, h23, l23);
    ((uint2*)dh)[t] = make_uint2(h01, h23);
    ((uint2*)dl)[t] = make_uint2(l01, l23);
}

// ---------------------------------------------------------------------------
// K1: E = exp(mask ? -inf : QK^T * inv) -> fp16 g_e + partial row sums.
// D streamed in 4 chunks of 32, cp.async double-buffered. (R14 fragment form)
// ---------------------------------------------------------------------------
__device__ __forceinline__ void k1_issue(uint32_t sb, int b, int q0, int k0, int ic, int buf, int tid)
{
    const int d0 = ic * 32;
#pragma unroll
    for (int i = 0; i < 8; i++) {
        const int idx = i * 256 + tid;     // 0..2047
        const int t = idx >> 9;            // tensor 0..3
        const int r = (idx >> 2) & 127;
        const int c = idx & 3;
        const __nv_bfloat16* base = (t == 0) ? g_qh : (t == 1) ? g_ql : (t == 2) ? g_kh : g_kl;
        const int row0 = (t < 2) ? q0 : k0;
        cp16(sb + K1_BUF(buf) + t * K1_CH + r * 80 + c * 16,
             base + ((size_t)(b * NQ + row0 + r)) * DHEAD + d0 + c * 8);
    }
}

__global__ __launch_bounds__(256, 2)
void qk_exp_kernel()
{
    extern __shared__ char smem[];
    const uint32_t sb = smem_u32(smem);
    const int tid = threadIdx.x;
    const int wid = tid >> 5;
    const int lane = tid & 31;
    const int wm = wid & 1;     // 64-row half
    const int wn = wid >> 1;    // 32-col group

    const int b  = blockIdx.z;
    const int q0 = blockIdx.y * 128;
    const int k0 = blockIdx.x * 128;

    k1_issue(sb, b, q0, k0, 0, 0, tid); CP_COMMIT();
    k1_issue(sb, b, q0, k0, 1, 1, tid); CP_COMMIT();

    float acc[4][4][4];
#pragma unroll
    for (int mt = 0; mt < 4; mt++)
#pragma unroll
        for (int nt = 0; nt < 4; nt++)
#pragma unroll
            for (int r = 0; r < 4; r++) acc[mt][nt][r] = 0.0f;

    const int lm = lane & 15, lq = lane >> 4;
    const int bn = lane & 7,  bk = (lane >> 3) & 1;

    for (int ic = 0; ic < 4; ic++) {
        const int buf = ic & 1;
        if (ic < 3) { CP_WAIT1(); } else { CP_WAIT0(); }
        __syncthreads();

        const uint32_t qb = sb + K1_BUF(buf);
        const uint32_t kb = sb + K1_BUF(buf) + 2 * K1_CH;
#pragma unroll
        for (int ks = 0; ks < 2; ks++) {
            uint32_t ah[4][4], al[4][4], bh[4][2], bl[4][2];
#pragma unroll
            for (int mt = 0; mt < 4; mt++) {
                const uint32_t a = qb + (wm * 64 + mt * 16 + lm) * 80 + (ks * 16 + lq * 8) * 2;
                ldsm_x4(a, ah[mt]);
                ldsm_x4(a + K1_CH, al[mt]);
            }
#pragma unroll
            for (int nt = 0; nt < 4; nt++) {
                const uint32_t a = kb + (wn * 32 + nt * 8 + bn) * 80 + (ks * 16 + bk * 8) * 2;
                ldsm_x2(a, bh[nt]);
                ldsm_x2(a + K1_CH, bl[nt]);
            }
#pragma unroll
            for (int mt = 0; mt < 4; mt++)
#pragma unroll
                for (int nt = 0; nt < 4; nt++) {
                    mma16816(acc[mt][nt], ah[mt], bh[nt][0], bh[nt][1]);
                    mma16816(acc[mt][nt], ah[mt], bl[nt][0], bl[nt][1]);
                    mma16816(acc[mt][nt], al[mt], bh[nt][0], bh[nt][1]);
                }
        }
        __syncthreads();
        if (ic + 2 < 4) { k1_issue(sb, b, q0, k0, ic + 2, (ic + 2) & 1, tid); CP_COMMIT(); }
    }

    // Hoist the epilogue mask load so its latency overlaps the staging phase.
    const int row_e  = tid & 127;
    const int half_e = tid >> 7;
    const uint2 mb = *(const uint2*)(g_mbits +
        ((size_t)b * NQ + q0 + row_e) * (NK / 32) + (k0 >> 5) + half_e * 2);

    // Stage scores through smem (overlays buffers; all loads consumed).
    float* sc = (float*)smem;
    {
        const int r0 = lane >> 2;
        const int c0 = (lane & 3) * 2;
#pragma unroll
        for (int mt = 0; mt < 4; mt++)
#pragma unroll
            for (int nt = 0; nt < 4; nt++) {
                const int rr = wm * 64 + mt * 16 + r0;
                const int cc = wn * 32 + nt * 8 + c0;
                sc[rr * SCSTRIDE + cc]           = acc[mt][nt][0];
                sc[rr * SCSTRIDE + cc + 1]       = acc[mt][nt][1];
                sc[(rr + 8) * SCSTRIDE + cc]     = acc[mt][nt][2];
                sc[(rr + 8) * SCSTRIDE + cc + 1] = acc[mt][nt][3];
            }
    }
    __syncthreads();

    {
        const size_t roff = ((size_t)b * NQ + q0 + row_e) * NK + k0 + half_e * 64;
        float rsum = 0.0f;
#pragma unroll
        for (int j = 0; j < 16; j++) {
            const float4 s4 = *(const float4*)&sc[row_e * SCSTRIDE + half_e * 64 + j * 4];
            const uint32_t w = (j < 8) ? mb.x : mb.y;
            const int sh = (j & 7) * 4;
            float e[4];
            const float ss[4] = {s4.x, s4.y, s4.z, s4.w};
#pragma unroll
            for (int jj = 0; jj < 4; jj++)
                e[jj] = ((w >> (sh + jj)) & 1u) ? 0.0f : __expf(ss[jj] * INV_SQRT_SCALE);
            // Round to fp16; accumulate row sum from the ROUNDED values so
            // softmax rows stay exactly self-consistent.
            const __half2 p01 = __floats2half2_rn(e[0], e[1]);
            const __half2 p23 = __floats2half2_rn(e[2], e[3]);
            rsum += (__low2float(p01) + __high2float(p01)) +
                    (__low2float(p23) + __high2float(p23));
            union { __half2 h2[2]; uint2 u; } pk;
            pk.h2[0] = p01; pk.h2[1] = p23;
            *(uint2*)(g_e + roff + j * 4) = pk.u;
        }
        sc[row_e * SCSTRIDE + 128 + half_e] = rsum;
    }
    __syncthreads();
    if (tid < 128)
        g_partial[((size_t)b * NQ + q0 + tid) * KBLOCKS + blockIdx.x] =
            sc[tid * SCSTRIDE + 128] + sc[tid * SCSTRIDE + 129];
}

// ---------------------------------------------------------------------------
// K2: att = E * rd (fp32 out, coalesced); ctx = (E @ (Vh+Vl)) * rd via
// 2-term fp16 MMA. NK streamed in 32-key chunks, cp.async double-buffered.
// ---------------------------------------------------------------------------
__device__ __forceinline__ void k2_issue(uint32_t sb, const __half* ebase, int b, int ic, int buf, int tid)
{
    const int n0 = ic * 32;
#pragma unroll
    for (int i = 0; i < 6; i++) {
        const int idx = i * 256 + tid;     // 0..1535
        if (idx < 512) {                   // E fp16 chunk: 128 rows x 4 c16
            const int r = idx >> 2;
            const int c = idx & 3;
            cp16(sb + K2_E(buf) + r * 80 + c * 16,
                 ebase + (size_t)r * NK + n0 + c * 8);
        } else {                           // V h/l: 32 rows x 16 c16 each
            const int j = idx - 512;
            const int h = j >> 9;
            const int r = (j >> 4) & 31;
            const int c = j & 15;
            const __half* base = h ? g_vl : g_vh;
            cp16(sb + K2_V(buf) + h * 8704 + r * 272 + c * 16,
                 base + ((size_t)(b * NK + n0 + r)) * DHEAD + c * 8);
        }
    }
}

__global__ __launch_bounds__(256, 2)
void av_kernel(float* __restrict__ att, float* __restrict__ ctx)
{
    extern __shared__ char smem[];
    const uint32_t sb = smem_u32(smem);
    float* rd = (float*)(smem + K2_OFF_RD);
    const int tid = threadIdx.x;
    const int wid = tid >> 5;
    const int lane = tid & 31;
    const int wm = wid & 1;
    const int wn = wid >> 1;

    const int b  = blockIdx.y;
    const int q0 = blockIdx.x * 128;

    if (tid < 128) {
        const float* p = &g_partial[((size_t)b * NQ + q0 + tid) * KBLOCKS];
        float s = 0.0f;
#pragma unroll
        for (int i = 0; i < KBLOCKS; i++) s += p[i];
        rd[tid] = 1.0f / s;
    }

    const __half* ebase = g_e + ((size_t)b * NQ + q0) * NK;
    float* attbase = att + ((size_t)b * NQ + q0) * NK;
    k2_issue(sb, ebase, b, 0, 0, tid); CP_COMMIT();
    k2_issue(sb, ebase, b, 1, 1, tid); CP_COMMIT();
    __syncthreads();   // rd[] visible before the mainloop reads it

    float acc[4][4][4];
#pragma unroll
    for (int mt = 0; mt < 4; mt++)
#pragma unroll
        for (int nt = 0; nt < 4; nt++)
#pragma unroll
            for (int r = 0; r < 4; r++) acc[mt][nt][r] = 0.0f;

    const int lm = lane & 15, lq = lane >> 4;

    for (int ic = 0; ic < NK / 32; ic++) {
        const int buf = ic & 1;
        const int n0 = ic * 32;
        if (ic < NK / 32 - 1) { CP_WAIT1(); } else { CP_WAIT0(); }
        __syncthreads();

        // ---- MMA: ctx += E @ (Vh + Vl), 2-term fp16 ----
        const uint32_t vb = sb + K2_V(buf);
#pragma unroll
        for (int ks = 0; ks < 2; ks++) {
            uint32_t eh[4][4];
#pragma unroll
            for (int mt = 0; mt < 4; mt++) {
                const uint32_t a = sb + K2_E(buf) + (wm * 64 + mt * 16 + lm) * 80
                                 + (ks * 16 + lq * 8) * 2;
                ldsm_x4(a, eh[mt]);
            }
#pragma unroll
            for (int ntp = 0; ntp < 2; ntp++) {
                uint32_t vh4[4], vl4[4];
                const uint32_t a = vb + (ks * 16 + lm) * 272 + (wn * 32 + ntp * 16 + lq * 8) * 2;
                ldsm_x4t(a, vh4);
                ldsm_x4t(a + 8704, vl4);
#pragma unroll
                for (int mt = 0; mt < 4; mt++) {
                    mma16816h(acc[mt][ntp * 2],     eh[mt], vh4[0], vh4[1]);
                    mma16816h(acc[mt][ntp * 2 + 1], eh[mt], vh4[2], vh4[3]);
                }
#pragma unroll
                for (int mt = 0; mt < 4; mt++) {
                    mma16816h(acc[mt][ntp * 2],     eh[mt], vl4[0], vl4[1]);
                    mma16816h(acc[mt][ntp * 2 + 1], eh[mt], vl4[2], vl4[3]);
                }
            }
        }

        // ---- att output: att = E * rd (COALESCED: 8 threads per row) ----
#pragma unroll
        for (int i = 0; i < 4; i++) {
            const int idx = i * 256 + tid;    // 0..1023
            const int r = idx >> 3;           // 0..127
            const int c4 = idx & 7;           // float4 column group
            const uint2 ev = *(const uint2*)(smem + K2_E(buf) + r * 80 + c4 * 8);
            const __half2 h01 = *(const __half2*)&ev.x;
            const __half2 h23 = *(const __half2*)&ev.y;
            const float rr = rd[r];
            *(float4*)(attbase + (size_t)r * NK + n0 + c4 * 4) = make_float4(
                __low2float(h01) * rr, __high2float(h01) * rr,
                __low2float(h23) * rr, __high2float(h23) * rr);
        }
        __syncthreads();
        if (ic + 2 < NK / 32) { k2_issue(sb, ebase, b, ic + 2, (ic + 2) & 1, tid); CP_COMMIT(); }
    }

    // rd values are needed after the staging overlays smem: keep in register.
    const int row_a = tid & 127;
    const float rr_a = rd[row_a];
    __syncthreads();

    // Stage ctx through smem for coalesced writes (overlays buffers).
    float* sc = (float*)smem;
    {
        const int r0 = lane >> 2;
        const int c0 = (lane & 3) * 2;
#pragma unroll
        for (int mt = 0; mt < 4; mt++)
#pragma unroll
            for (int nt = 0; nt < 4; nt++) {
                const int rr = wm * 64 + mt * 16 + r0;
                const int cc = wn * 32 + nt * 8 + c0;
                sc[rr * K2_SCSTRIDE + cc]           = acc[mt][nt][0];
                sc[rr * K2_SCSTRIDE + cc + 1]       = acc[mt][nt][1];
                sc[(rr + 8) * K2_SCSTRIDE + cc]     = acc[mt][nt][2];
                sc[(rr + 8) * K2_SCSTRIDE + cc + 1] = acc[mt][nt][3];
            }
    }
    __syncthreads();
    {
        const int half = tid >> 7;
        float* o = ctx + ((size_t)b * NQ + q0 + row_a) * DHEAD + half * 64;
#pragma unroll
        for (int j = 0; j < 16; j++) {
            const float4 c4 = *(const float4*)&sc[row_a * K2_SCSTRIDE + half * 64 + j * 4];
            *(float4*)(o + j * 4) = make_float4(c4.x * rr_a, c4.y * rr_a, c4.z * rr_a, c4.w * rr_a);
        }
    }
}

// ---------------------------------------------------------------------------
extern "C" void kernel_launch(void* const* d_in, const int* in_sizes, int n_in,
                              void* d_out, int out_size)
{
    const float* q = (const float*)d_in[0];
    const float* k = (const float*)d_in[1];
    const float* v = (const float*)d_in[2];
    const void*  mask = d_in[3];

    float* out = (float*)d_out;
    float* ctx = out;                                   // [B, NQ, D]
    float* att = out + (size_t)BATCH * NQ * DHEAD;      // [B, NQ, NK]

    cudaFuncSetAttribute(qk_exp_kernel, cudaFuncAttributeMaxDynamicSharedMemorySize, SMEM_K1);
    cudaFuncSetAttribute(av_kernel,     cudaFuncAttributeMaxDynamicSharedMemorySize, SMEM_K2);

    detect_mask_kernel<<<1, 256>>>((const unsigned char*)mask);
    pack_mask_kernel<<<(int)(MBITS_WORDS / 256), 256>>>(mask);
    prep_kernel<<<dim3(4096, 3), 256>>>(q, k, v);

    dim3 g1(NK / 128, NQ / 128, BATCH);
    qk_exp_kernel<<<g1, 256, SMEM_K1>>>();

    dim3 g2(NQ / 128, BATCH);
    av_kernel<<<g2, 256, SMEM_K2>>>(att, ctx);
}

// round 17
// speedup vs baseline: 2.0097x; 1.1293x over previous
// ---------------------------------------------------------------------------
// R17 = R16 with K1's QK product switched from 3-term bf16 (hh+hl+lh) to
// ASYMMETRIC 2-term fp16: Qh*(Kh+Kl). Residual Ql*K ~ 2^-11 -> att rel err
// +2.5e-4 (combined with fp16-E still << 1e-3). K1 MMA count -33%, Q LDSM
// and Q cp.async halved, prep drops Ql stream. K2 unchanged.
// Prediction: K1 218 -> ~160-175, total 430 -> ~375-390; rel_err ~3-4e-4.
// ---------------------------------------------------------------------------
#include <cuda_runtime.h>
#include <cuda_bf16.h>
#include <cuda_fp16.h>
#include <cstdint>

#define BATCH 16
#define NQ 2048
#define NK 2048
#define DHEAD 128
#define KBLOCKS 16
#define INV_SQRT_SCALE 0.08838834764831845f  // 1/sqrt(128)

// ---------------------------------------------------------------------------
// Global scratch: fp16 Qh; fp16 hi/lo K, V; fp16 unnormalized E; bit mask.
// ---------------------------------------------------------------------------
#define TENSOR_ELEMS ((size_t)BATCH * NQ * DHEAD)
__device__ __align__(16) __half g_qh[TENSOR_ELEMS];
__device__ __align__(16) __half g_kh[TENSOR_ELEMS];
__device__ __align__(16) __half g_kl[TENSOR_ELEMS];
__device__ __align__(16) __half g_vh[TENSOR_ELEMS];
__device__ __align__(16) __half g_vl[TENSOR_ELEMS];
__device__ __align__(16) __half g_e[(size_t)BATCH * NQ * NK];   // 134 MB
__device__ float g_partial[(size_t)BATCH * NQ * KBLOCKS];
__device__ int g_mask_mode;   // 0 = bytes, 1 = int32, 2 = float32
#define MBITS_WORDS ((size_t)BATCH * NQ * NK / 32)
__device__ __align__(16) uint32_t g_mbits[MBITS_WORDS];

// ---------------------------------------------------------------------------
// K1 smem: 2 bufs x 3 tensors (Qh,Kh,Kl), each 128 rows x 32 fp16, row
// stride 80 B -> 30720 B per buf, 61440 total. Score staging (128 x 132 f32
// = 67584 B) overlays the buffers (is the size-setter).
// ---------------------------------------------------------------------------
#define K1_CH 10240                        // 128 * 80
#define K1_BUF(b) ((b) * 3 * K1_CH)        // 30720 per buf
#define SMEM_K1 67584
#define SCSTRIDE 132

// ---------------------------------------------------------------------------
// K2 smem: E fp16 chunk (128 x 32, stride 80 B) x2 bufs at 0; V fp16 chunk
// (32 x 128 h+l, stride 272 B) x2 bufs at 20480; rd[128] at 67584.
// Ctx staging (128 x 132 f32 = 67584) overlays the buffers at the end.
// ---------------------------------------------------------------------------
#define K2_E(b) ((b) * 10240)              // 128*80
#define K2_V(b) (20480 + (b) * 17408)      // vh 8704 + vl 8704
#define K2_OFF_RD 67584
#define SMEM_K2 68096
#define K2_SCSTRIDE 132

// ---------------------------------------------------------------------------
// PTX primitives (portable, base sm_103 target)
// ---------------------------------------------------------------------------
__device__ __forceinline__ uint32_t smem_u32(const void* p) {
    uint32_t a;
    asm("{ .reg .u64 t; cvta.to.shared.u64 t, %1; cvt.u32.u64 %0, t; }" : "=r"(a) : "l"(p));
    return a;
}
__device__ __forceinline__ void ldsm_x4(uint32_t a, uint32_t r[4]) {
    asm volatile("ldmatrix.sync.aligned.m8n8.x4.shared.b16 {%0,%1,%2,%3}, [%4];"
        : "=r"(r[0]), "=r"(r[1]), "=r"(r[2]), "=r"(r[3]) : "r"(a));
}
__device__ __forceinline__ void ldsm_x2(uint32_t a, uint32_t r[2]) {
    asm volatile("ldmatrix.sync.aligned.m8n8.x2.shared.b16 {%0,%1}, [%2];"
        : "=r"(r[0]), "=r"(r[1]) : "r"(a));
}
__device__ __forceinline__ void ldsm_x4t(uint32_t a, uint32_t r[4]) {
    asm volatile("ldmatrix.sync.aligned.m8n8.x4.trans.shared.b16 {%0,%1,%2,%3}, [%4];"
        : "=r"(r[0]), "=r"(r[1]), "=r"(r[2]), "=r"(r[3]) : "r"(a));
}
__device__ __forceinline__ void mma16816h(float c[4], const uint32_t a[4], uint32_t b0, uint32_t b1) {
    asm volatile("mma.sync.aligned.m16n8k16.row.col.f32.f16.f16.f32 "
        "{%0,%1,%2,%3}, {%4,%5,%6,%7}, {%8,%9}, {%0,%1,%2,%3};"
        : "+f"(c[0]), "+f"(c[1]), "+f"(c[2]), "+f"(c[3])
        : "r"(a[0]), "r"(a[1]), "r"(a[2]), "r"(a[3]), "r"(b0), "r"(b1));
}
__device__ __forceinline__ void cp16(uint32_t dst, const void* src) {
    asm volatile("cp.async.cg.shared.global [%0], [%1], 16;" :: "r"(dst), "l"(src));
}
#define CP_COMMIT() asm volatile("cp.async.commit_group;")
#define CP_WAIT1()  asm volatile("cp.async.wait_group 1;")
#define CP_WAIT0()  asm volatile("cp.async.wait_group 0;")

__device__ __forceinline__ uint32_t pack2h(__half a, __half b) {
    __half2 t = __halves2half2(a, b);
    return *reinterpret_cast<uint32_t*>(&t);
}
__device__ __forceinline__ void split2h(float x, float y, uint32_t& h, uint32_t& l) {
    __half hx = __float2half_rn(x), hy = __float2half_rn(y);
    __half lx = __float2half_rn(x - __half2float(hx));
    __half ly = __float2half_rn(y - __half2float(hy));
    h = pack2h(hx, hy);
    l = pack2h(lx, ly);
}

// ---------------------------------------------------------------------------
__global__ void detect_mask_kernel(const unsigned char* __restrict__ m)
{
    const int tid = threadIdx.x;
    int mis = 0, ftail = 0;
    for (int i = tid * 16; i < tid * 16 + 16; i++) {
        const unsigned char b = m[i];
        if (b) {
            const int r = i & 3;
            if (r == 1) mis = 1;
            else if (r == 2) { if (b != 0x80) mis = 1; else ftail = 1; }
            else if (r == 3) { if (b != 0x3F) mis = 1; else ftail = 1; }
        }
    }
    const int anyMis = __syncthreads_or(mis);
    const int anyF   = __syncthreads_or(ftail);
    if (tid == 0) g_mask_mode = anyMis ? 0 : (anyF ? 2 : 1);
}

__global__ __launch_bounds__(256) void pack_mask_kernel(const void* __restrict__ mask)
{
    const size_t w = (size_t)blockIdx.x * 256 + threadIdx.x;
    const int mode = g_mask_mode;
    uint32_t bits = 0;
    if (mode == 0) {
        const uint4* p = (const uint4*)((const unsigned char*)mask + w * 32);
#pragma unroll
        for (int i = 0; i < 2; i++) {
            const uint4 v = p[i];
            const uint32_t ws[4] = {v.x, v.y, v.z, v.w};
#pragma unroll
            for (int k = 0; k < 4; k++)
#pragma unroll
                for (int byt = 0; byt < 4; byt++)
                    bits |= (uint32_t)(((ws[k] >> (8 * byt)) & 0xffu) != 0u) << (i * 16 + k * 4 + byt);
        }
    } else {
        const uint4* p = (const uint4*)((const uint32_t*)mask + w * 32);
#pragma unroll
        for (int i = 0; i < 8; i++) {
            const uint4 v = p[i];
            bits |= (uint32_t)(v.x != 0u) << (i * 4 + 0);
            bits |= (uint32_t)(v.y != 0u) << (i * 4 + 1);
            bits |= (uint32_t)(v.z != 0u) << (i * 4 + 2);
            bits |= (uint32_t)(v.w != 0u) << (i * 4 + 3);
        }
    }
    g_mbits[w] = bits;
}

__global__ __launch_bounds__(256) void prep_kernel(
    const float* __restrict__ q, const float* __restrict__ k, const float* __restrict__ v)
{
    const size_t t = (size_t)blockIdx.x * 256 + threadIdx.x;   // float4 index
    if (blockIdx.y == 0) {                 // Q -> fp16 hi only
        const float4 x = ((const float4*)q)[t];
        const uint32_t h01 = pack2h(__float2half_rn(x.x), __float2half_rn(x.y));
        const uint32_t h23 = pack2h(__float2half_rn(x.z), __float2half_rn(x.w));
        ((uint2*)g_qh)[t] = make_uint2(h01, h23);
        return;
    }
    const float* src = (blockIdx.y == 1) ? k : v;
    __half* dh = (blockIdx.y == 1) ? g_kh : g_vh;
    __half* dl = (blockIdx.y == 1) ? g_kl : g_vl;
    const float4 x = ((const float4*)src)[t];
    uint32_t h01, l01, h23, l23;
    split2h(x.x, x.y, h01, l01);
    split2h(x.z, x.w, h23, l23);
    ((uint2*)dh)[t] = make_uint2(h01, h23);
    ((uint2*)dl)[t] = make_uint2(l01, l23);
}

// ---------------------------------------------------------------------------
// K1: E = exp(mask ? -inf : QK^T * inv) -> fp16 g_e + partial row sums.
// Asymmetric 2-term fp16: Qh*(Kh + Kl). D streamed in 4 chunks of 32,
// cp.async double-buffered.
// ---------------------------------------------------------------------------
__device__ __forceinline__ void k1_issue(uint32_t sb, int b, int q0, int k0, int ic, int buf, int tid)
{
    const int d0 = ic * 32;
#pragma unroll
    for (int i = 0; i < 6; i++) {
        const int idx = i * 256 + tid;     // 0..1535
        const int t = idx >> 9;            // tensor 0..2 (Qh, Kh, Kl)
        const int r = (idx >> 2) & 127;
        const int c = idx & 3;
        const __half* base = (t == 0) ? g_qh : (t == 1) ? g_kh : g_kl;
        const int row0 = (t == 0) ? q0 : k0;
        cp16(sb + K1_BUF(buf) + t * K1_CH + r * 80 + c * 16,
             base + ((size_t)(b * NQ + row0 + r)) * DHEAD + d0 + c * 8);
    }
}

__global__ __launch_bounds__(256, 2)
void qk_exp_kernel()
{
    extern __shared__ char smem[];
    const uint32_t sb = smem_u32(smem);
    const int tid = threadIdx.x;
    const int wid = tid >> 5;
    const int lane = tid & 31;
    const int wm = wid & 1;     // 64-row half
    const int wn = wid >> 1;    // 32-col group

    const int b  = blockIdx.z;
    const int q0 = blockIdx.y * 128;
    const int k0 = blockIdx.x * 128;

    k1_issue(sb, b, q0, k0, 0, 0, tid); CP_COMMIT();
    k1_issue(sb, b, q0, k0, 1, 1, tid); CP_COMMIT();

    float acc[4][4][4];
#pragma unroll
    for (int mt = 0; mt < 4; mt++)
#pragma unroll
        for (int nt = 0; nt < 4; nt++)
#pragma unroll
            for (int r = 0; r < 4; r++) acc[mt][nt][r] = 0.0f;

    const int lm = lane & 15, lq = lane >> 4;
    const int bn = lane & 7,  bk = (lane >> 3) & 1;

    for (int ic = 0; ic < 4; ic++) {
        const int buf = ic & 1;
        if (ic < 3) { CP_WAIT1(); } else { CP_WAIT0(); }
        __syncthreads();

        const uint32_t qb = sb + K1_BUF(buf);
        const uint32_t kb = sb + K1_BUF(buf) + K1_CH;
#pragma unroll
        for (int ks = 0; ks < 2; ks++) {
            uint32_t ah[4][4], bh[4][2], bl[4][2];
#pragma unroll
            for (int mt = 0; mt < 4; mt++) {
                const uint32_t a = qb + (wm * 64 + mt * 16 + lm) * 80 + (ks * 16 + lq * 8) * 2;
                ldsm_x4(a, ah[mt]);
            }
#pragma unroll
            for (int nt = 0; nt < 4; nt++) {
                const uint32_t a = kb + (wn * 32 + nt * 8 + bn) * 80 + (ks * 16 + bk * 8) * 2;
                ldsm_x2(a, bh[nt]);
                ldsm_x2(a + K1_CH, bl[nt]);
            }
#pragma unroll
            for (int mt = 0; mt < 4; mt++)
#pragma unroll
                for (int nt = 0; nt < 4; nt++) {
                    mma16816h(acc[mt][nt], ah[mt], bh[nt][0], bh[nt][1]);
                    mma16816h(acc[mt][nt], ah[mt], bl[nt][0], bl[nt][1]);
                }
        }
        __syncthreads();
        if (ic + 2 < 4) { k1_issue(sb, b, q0, k0, ic + 2, (ic + 2) & 1, tid); CP_COMMIT(); }
    }

    // Hoist the epilogue mask load so its latency overlaps the staging phase.
    const int row_e  = tid & 127;
    const int half_e = tid >> 7;
    const uint2 mb = *(const uint2*)(g_mbits +
        ((size_t)b * NQ + q0 + row_e) * (NK / 32) + (k0 >> 5) + half_e * 2);

    // Stage scores through smem (overlays buffers; all loads consumed).
    float* sc = (float*)smem;
    {
        const int r0 = lane >> 2;
        const int c0 = (lane & 3) * 2;
#pragma unroll
        for (int mt = 0; mt < 4; mt++)
#pragma unroll
            for (int nt = 0; nt < 4; nt++) {
                const int rr = wm * 64 + mt * 16 + r0;
                const int cc = wn * 32 + nt * 8 + c0;
                sc[rr * SCSTRIDE + cc]           = acc[mt][nt][0];
                sc[rr * SCSTRIDE + cc + 1]       = acc[mt][nt][1];
                sc[(rr + 8) * SCSTRIDE + cc]     = acc[mt][nt][2];
                sc[(rr + 8) * SCSTRIDE + cc + 1] = acc[mt][nt][3];
            }
    }
    __syncthreads();

    {
        const size_t roff = ((size_t)b * NQ + q0 + row_e) * NK + k0 + half_e * 64;
        float rsum = 0.0f;
#pragma unroll
        for (int j = 0; j < 16; j++) {
            const float4 s4 = *(const float4*)&sc[row_e * SCSTRIDE + half_e * 64 + j * 4];
            const uint32_t w = (j < 8) ? mb.x : mb.y;
            const int sh = (j & 7) * 4;
            float e[4];
            const float ss[4] = {s4.x, s4.y, s4.z, s4.w};
#pragma unroll
            for (int jj = 0; jj < 4; jj++)
                e[jj] = ((w >> (sh + jj)) & 1u) ? 0.0f : __expf(ss[jj] * INV_SQRT_SCALE);
            // Round to fp16; accumulate row sum from the ROUNDED values so
            // softmax rows stay exactly self-consistent.
            const __half2 p01 = __floats2half2_rn(e[0], e[1]);
            const __half2 p23 = __floats2half2_rn(e[2], e[3]);
            rsum += (__low2float(p01) + __high2float(p01)) +
                    (__low2float(p23) + __high2float(p23));
            union { __half2 h2[2]; uint2 u; } pk;
            pk.h2[0] = p01; pk.h2[1] = p23;
            *(uint2*)(g_e + roff + j * 4) = pk.u;
        }
        sc[row_e * SCSTRIDE + 128 + half_e] = rsum;
    }
    __syncthreads();
    if (tid < 128)
        g_partial[((size_t)b * NQ + q0 + tid) * KBLOCKS + blockIdx.x] =
            sc[tid * SCSTRIDE + 128] + sc[tid * SCSTRIDE + 129];
}

// ---------------------------------------------------------------------------
// K2: att = E * rd (fp32 out, coalesced); ctx = (E @ (Vh+Vl)) * rd via
// 2-term fp16 MMA. NK streamed in 32-key chunks, cp.async double-buffered.
// ---------------------------------------------------------------------------
__device__ __forceinline__ void k2_issue(uint32_t sb, const __half* ebase, int b, int ic, int buf, int tid)
{
    const int n0 = ic * 32;
#pragma unroll
    for (int i = 0; i < 6; i++) {
        const int idx = i * 256 + tid;     // 0..1535
        if (idx < 512) {                   // E fp16 chunk: 128 rows x 4 c16
            const int r = idx >> 2;
            const int c = idx & 3;
            cp16(sb + K2_E(buf) + r * 80 + c * 16,
                 ebase + (size_t)r * NK + n0 + c * 8);
        } else {                           // V h/l: 32 rows x 16 c16 each
            const int j = idx - 512;
            const int h = j >> 9;
            const int r = (j >> 4) & 31;
            const int c = j & 15;
            const __half* base = h ? g_vl : g_vh;
            cp16(sb + K2_V(buf) + h * 8704 + r * 272 + c * 16,
                 base + ((size_t)(b * NK + n0 + r)) * DHEAD + c * 8);
        }
    }
}

__global__ __launch_bounds__(256, 2)
void av_kernel(float* __restrict__ att, float* __restrict__ ctx)
{
    extern __shared__ char smem[];
    const uint32_t sb = smem_u32(smem);
    float* rd = (float*)(smem + K2_OFF_RD);
    const int tid = threadIdx.x;
    const int wid = tid >> 5;
    const int lane = tid & 31;
    const int wm = wid & 1;
    const int wn = wid >> 1;

    const int b  = blockIdx.y;
    const int q0 = blockIdx.x * 128;

    if (tid < 128) {
        const float* p = &g_partial[((size_t)b * NQ + q0 + tid) * KBLOCKS];
        float s = 0.0f;
#pragma unroll
        for (int i = 0; i < KBLOCKS; i++) s += p[i];
        rd[tid] = 1.0f / s;
    }

    const __half* ebase = g_e + ((size_t)b * NQ + q0) * NK;
    float* attbase = att + ((size_t)b * NQ + q0) * NK;
    k2_issue(sb, ebase, b, 0, 0, tid); CP_COMMIT();
    k2_issue(sb, ebase, b, 1, 1, tid); CP_COMMIT();
    __syncthreads();   // rd[] visible before the mainloop reads it

    float acc[4][4][4];
#pragma unroll
    for (int mt = 0; mt < 4; mt++)
#pragma unroll
        for (int nt = 0; nt < 4; nt++)
#pragma unroll
            for (int r = 0; r < 4; r++) acc[mt][nt][r] = 0.0f;

    const int lm = lane & 15, lq = lane >> 4;

    for (int ic = 0; ic < NK / 32; ic++) {
        const int buf = ic & 1;
        const int n0 = ic * 32;
        if (ic < NK / 32 - 1) { CP_WAIT1(); } else { CP_WAIT0(); }
        __syncthreads();

        // ---- MMA: ctx += E @ (Vh + Vl), 2-term fp16 ----
        const uint32_t vb = sb + K2_V(buf);
#pragma unroll
        for (int ks = 0; ks < 2; ks++) {
            uint32_t eh[4][4];
#pragma unroll
            for (int mt = 0; mt < 4; mt++) {
                const uint32_t a = sb + K2_E(buf) + (wm * 64 + mt * 16 + lm) * 80
                                 + (ks * 16 + lq * 8) * 2;
                ldsm_x4(a, eh[mt]);
            }
#pragma unroll
            for (int ntp = 0; ntp < 2; ntp++) {
                uint32_t vh4[4], vl4[4];
                const uint32_t a = vb + (ks * 16 + lm) * 272 + (wn * 32 + ntp * 16 + lq * 8) * 2;
                ldsm_x4t(a, vh4);
                ldsm_x4t(a + 8704, vl4);
#pragma unroll
                for (int mt = 0; mt < 4; mt++) {
                    mma16816h(acc[mt][ntp * 2],     eh[mt], vh4[0], vh4[1]);
                    mma16816h(acc[mt][ntp * 2 + 1], eh[mt], vh4[2], vh4[3]);
                }
#pragma unroll
                for (int mt = 0; mt < 4; mt++) {
                    mma16816h(acc[mt][ntp * 2],     eh[mt], vl4[0], vl4[1]);
                    mma16816h(acc[mt][ntp * 2 + 1], eh[mt], vl4[2], vl4[3]);
                }
            }
        }

        // ---- att output: att = E * rd (COALESCED: 8 threads per row) ----
#pragma unroll
        for (int i = 0; i < 4; i++) {
            const int idx = i * 256 + tid;    // 0..1023
            const int r = idx >> 3;           // 0..127
            const int c4 = idx & 7;           // float4 column group
            const uint2 ev = *(const uint2*)(smem + K2_E(buf) + r * 80 + c4 * 8);
            const __half2 h01 = *(const __half2*)&ev.x;
            const __half2 h23 = *(const __half2*)&ev.y;
            const float rr = rd[r];
            *(float4*)(attbase + (size_t)r * NK + n0 + c4 * 4) = make_float4(
                __low2float(h01) * rr, __high2float(h01) * rr,
                __low2float(h23) * rr, __high2float(h23) * rr);
        }
        __syncthreads();
        if (ic + 2 < NK / 32) { k2_issue(sb, ebase, b, ic + 2, (ic + 2) & 1, tid); CP_COMMIT(); }
    }

    // rd values are needed after the staging overlays smem: keep in register.
    const int row_a = tid & 127;
    const float rr_a = rd[row_a];
    __syncthreads();

    // Stage ctx through smem for coalesced writes (overlays buffers).
    float* sc = (float*)smem;
    {
        const int r0 = lane >> 2;
        const int c0 = (lane & 3) * 2;
#pragma unroll
        for (int mt = 0; mt < 4; mt++)
#pragma unroll
            for (int nt = 0; nt < 4; nt++) {
                const int rr = wm * 64 + mt * 16 + r0;
                const int cc = wn * 32 + nt * 8 + c0;
                sc[rr * K2_SCSTRIDE + cc]           = acc[mt][nt][0];
                sc[rr * K2_SCSTRIDE + cc + 1]       = acc[mt][nt][1];
                sc[(rr + 8) * K2_SCSTRIDE + cc]     = acc[mt][nt][2];
                sc[(rr + 8) * K2_SCSTRIDE + cc + 1] = acc[mt][nt][3];
            }
    }
    __syncthreads();
    {
        const int half = tid >> 7;
        float* o = ctx + ((size_t)b * NQ + q0 + row_a) * DHEAD + half * 64;
#pragma unroll
        for (int j = 0; j < 16; j++) {
            const float4 c4 = *(const float4*)&sc[row_a * K2_SCSTRIDE + half * 64 + j * 4];
            *(float4*)(o + j * 4) = make_float4(c4.x * rr_a, c4.y * rr_a, c4.z * rr_a, c4.w * rr_a);
        }
    }
}

// ---------------------------------------------------------------------------
extern "C" void kernel_launch(void* const* d_in, const int* in_sizes, int n_in,
                              void* d_out, int out_size)
{
    const float* q = (const float*)d_in[0];
    const float* k = (const float*)d_in[1];
    const float* v = (const float*)d_in[2];
    const void*  mask = d_in[3];

    float* out = (float*)d_out;
    float* ctx = out;                                   // [B, NQ, D]
    float* att = out + (size_t)BATCH * NQ * DHEAD;      // [B, NQ, NK]

    cudaFuncSetAttribute(qk_exp_kernel, cudaFuncAttributeMaxDynamicSharedMemorySize, SMEM_K1);
    cudaFuncSetAttribute(av_kernel,     cudaFuncAttributeMaxDynamicSharedMemorySize, SMEM_K2);

    detect_mask_kernel<<<1, 256>>>((const unsigned char*)mask);
    pack_mask_kernel<<<(int)(MBITS_WORDS / 256), 256>>>(mask);
    prep_kernel<<<dim3(4096, 3), 256>>>(q, k, v);

    dim3 g1(NK / 128, NQ / 128, BATCH);
    qk_exp_kernel<<<g1, 256, SMEM_K1>>>();

    dim3 g2(NQ / 128, BATCH);
    av_kernel<<<g2, 256, SMEM_K2>>>(att, ctx);
}